// round 7
// baseline (speedup 1.0000x reference)
#include <cuda_runtime.h>
#include <cuda_bf16.h>
#include <math.h>
#include <stdint.h>

// ---------------- problem constants ----------------
constexpr int kB  = 2;
constexpr int kT  = 2048;
constexpr int kD  = 1024;
constexpr int kH  = 16;
constexpr int kDH = 64;
constexpr int kFF = 4096;
constexpr int kE  = 4;
constexpr int kNT = kB * kT;           // 4096 tokens
constexpr float kEPS = 1e-5f;
constexpr int kPersist = 296;          // 2 CTAs x 148 SMs

// ---------------- scratch (device globals: allocation-free) ----------------
__device__ float g_proj[kNT * kD];
__device__ float g_x1[kNT * kD];
__device__ float g_y[kNT * kD];
__device__ int   g_cnt[kE];
__device__ int   g_list[kE * kNT];

// bf16 hi/lo planes (activations)
__device__ __nv_bfloat16 g_xb_h[kNT * kD],  g_xb_l[kNT * kD];
__device__ __nv_bfloat16 g_qb_h[kNT * kD],  g_qb_l[kNT * kD];
__device__ __nv_bfloat16 g_kb_h[kNT * kD],  g_kb_l[kNT * kD];
__device__ __nv_bfloat16 g_vb_h[kNT * kD],  g_vb_l[kNT * kD];
__device__ __nv_bfloat16 g_ab_h[kNT * kD],  g_ab_l[kNT * kD];     // attn out
__device__ __nv_bfloat16 g_x1b_h[kNT * kD], g_x1b_l[kNT * kD];
__device__ __nv_bfloat16 g_hb_h[(size_t)kNT * kFF], g_hb_l[(size_t)kNT * kFF];

// bf16 hi/lo planes (transposed weights, [N][K] K-major)
__device__ __nv_bfloat16 g_w4t_h[4 * kD * kD], g_w4t_l[4 * kD * kD];   // Wq,Wk,Wv,Wo
__device__ __nv_bfloat16 g_w1t_h[(size_t)kE * kFF * kD], g_w1t_l[(size_t)kE * kFF * kD];
__device__ __nv_bfloat16 g_w2t_h[(size_t)kE * kFF * kD], g_w2t_l[(size_t)kE * kFF * kD];

// ==================== PTX helpers (base sm_103 features only) ====================
__device__ __forceinline__ uint32_t smem_u32(const void* p) {
    uint32_t a;
    asm("{ .reg .u64 t; cvta.to.shared.u64 t, %1; cvt.u32.u64 %0, t; }" : "=r"(a) : "l"(p));
    return a;
}

__device__ __forceinline__ void cp_async16(uint32_t s, const void* g, int sz) {
    asm volatile("cp.async.cg.shared.global [%0], [%1], 16, %2;"
                 :: "r"(s), "l"(g), "r"(sz) : "memory");
}
#define CP_COMMIT()  asm volatile("cp.async.commit_group;" ::: "memory")
#define CP_WAIT(n)   asm volatile("cp.async.wait_group %0;" :: "n"(n) : "memory")

__device__ __forceinline__ void ldsm_x4(uint32_t& r0, uint32_t& r1, uint32_t& r2,
                                        uint32_t& r3, uint32_t addr) {
    asm volatile("ldmatrix.sync.aligned.m8n8.x4.shared.b16 {%0,%1,%2,%3}, [%4];"
                 : "=r"(r0), "=r"(r1), "=r"(r2), "=r"(r3) : "r"(addr));
}
__device__ __forceinline__ void ldsm_x4_t(uint32_t& r0, uint32_t& r1, uint32_t& r2,
                                          uint32_t& r3, uint32_t addr) {
    asm volatile("ldmatrix.sync.aligned.m8n8.x4.trans.shared.b16 {%0,%1,%2,%3}, [%4];"
                 : "=r"(r0), "=r"(r1), "=r"(r2), "=r"(r3) : "r"(addr));
}

__device__ __forceinline__ void mma16816(float* d, const uint32_t* a,
                                         uint32_t b0, uint32_t b1) {
    asm volatile("mma.sync.aligned.m16n8k16.row.col.f32.bf16.bf16.f32 "
                 "{%0,%1,%2,%3}, {%4,%5,%6,%7}, {%8,%9}, {%0,%1,%2,%3};"
                 : "+f"(d[0]), "+f"(d[1]), "+f"(d[2]), "+f"(d[3])
                 : "r"(a[0]), "r"(a[1]), "r"(a[2]), "r"(a[3]), "r"(b0), "r"(b1));
}

// split (f0,f1) into packed bf16 hi and lo planes
__device__ __forceinline__ void split2(float f0, float f1, uint32_t& h, uint32_t& l) {
    __nv_bfloat162 hv = __floats2bfloat162_rn(f0, f1);
    float r0 = f0 - __bfloat162float(hv.x);
    float r1 = f1 - __bfloat162float(hv.y);
    __nv_bfloat162 lv = __floats2bfloat162_rn(r0, r1);
    h = *reinterpret_cast<uint32_t*>(&hv);
    l = *reinterpret_cast<uint32_t*>(&lv);
}

// ==================== mma.sync split-bf16 GEMM ====================
// Block tile 128x128, 256 threads (8 warps, 4Mx2N), warp tile 32x64, K-chunk 32.
constexpr int kRowB   = 80;                    // padded row bytes (32 bf16 + 8 pad)
constexpr int kPlaneB = 128 * kRowB;           // 10240
constexpr int kStageB = 4 * kPlaneB;           // Ah Al Bh Bl = 40960
constexpr int GEMM_SMEM = 2 * kStageB;         // 81920

struct GemmPtrs {
    const __nv_bfloat16 *aH0, *aL0, *aH1, *aL1;
    const __nv_bfloat16 *bH0, *bL0, *bH1, *bL1;
    int v0, v1, c8;
};

__device__ __forceinline__ void fill_stage(uint32_t sb, int k0, const GemmPtrs& P)
{
    int o = (threadIdx.x >> 2) * kRowB + (threadIdx.x & 3) * 16;
    int g = k0 + P.c8;
    cp_async16(sb + o,                       P.aH0 + g, P.v0 ? 16 : 0);
    cp_async16(sb + o + 64 * kRowB,          P.aH1 + g, P.v1 ? 16 : 0);
    cp_async16(sb + kPlaneB + o,             P.aL0 + g, P.v0 ? 16 : 0);
    cp_async16(sb + kPlaneB + o + 64*kRowB,  P.aL1 + g, P.v1 ? 16 : 0);
    cp_async16(sb + 2*kPlaneB + o,           P.bH0 + g, 16);
    cp_async16(sb + 2*kPlaneB + o + 64*kRowB,P.bH1 + g, 16);
    cp_async16(sb + 3*kPlaneB + o,           P.bL0 + g, 16);
    cp_async16(sb + 3*kPlaneB + o + 64*kRowB,P.bL1 + g, 16);
}

// mode 0: C = acc + bias (fp32)
// mode 1: relu(acc+bias) -> Chi/Clo bf16 planes
// mode 2: (acc+bias)*scale -> Chi/Clo bf16 planes
__device__ __forceinline__ void gemm_tile(
    const __nv_bfloat16* __restrict__ Ah, const __nv_bfloat16* __restrict__ Al,
    const __nv_bfloat16* __restrict__ Bh, const __nv_bfloat16* __restrict__ Bl,
    const float* __restrict__ bias, int K, int count, const int* __restrict__ list,
    int mode, float* __restrict__ C,
    __nv_bfloat16* __restrict__ Chi, __nv_bfloat16* __restrict__ Clo, int ldc,
    float scale, int rowBase, int colBase, uint32_t smb)
{
    const int tid  = threadIdx.x;
    const int wid  = tid >> 5, lane = tid & 31;

    GemmPtrs P;
    {
        int r0 = tid >> 2;
        int gr0 = rowBase + r0, gr1 = rowBase + r0 + 64;
        P.v0 = gr0 < count;
        P.v1 = gr1 < count;
        int rr0 = P.v0 ? (list ? list[gr0] : gr0) : 0;
        int rr1 = P.v1 ? (list ? list[gr1] : gr1) : 0;
        P.aH0 = Ah + (size_t)rr0 * K;  P.aL0 = Al + (size_t)rr0 * K;
        P.aH1 = Ah + (size_t)rr1 * K;  P.aL1 = Al + (size_t)rr1 * K;
        P.bH0 = Bh + (size_t)(colBase + r0) * K;
        P.bH1 = Bh + (size_t)(colBase + r0 + 64) * K;
        P.bL0 = Bl + (size_t)(colBase + r0) * K;
        P.bL1 = Bl + (size_t)(colBase + r0 + 64) * K;
        P.c8  = (tid & 3) * 8;
    }

    const int wM = (wid & 3) * 32;
    const int wN = (wid >> 2) * 64;

    float acc[2][8][4];
    #pragma unroll
    for (int i = 0; i < 2; i++)
        #pragma unroll
        for (int j = 0; j < 8; j++)
            #pragma unroll
            for (int d = 0; d < 4; d++) acc[i][j][d] = 0.f;

    const int nc = K / 32;
    fill_stage(smb, 0, P);
    CP_COMMIT();

    const int aRowSel = lane & 15, aColSel = (lane >> 4) * 16;
    const int bRowSel = (lane & 7) + ((lane >> 4) & 1) * 8;
    const int bColSel = ((lane >> 3) & 1) * 16;

    for (int c = 0; c < nc; c++) {
        CP_WAIT(0);
        __syncthreads();
        if (c + 1 < nc) {
            fill_stage(smb + ((c + 1) & 1) * kStageB, (c + 1) * 32, P);
            CP_COMMIT();
        }

        uint32_t st = smb + (c & 1) * kStageB;
        #pragma unroll
        for (int s = 0; s < 2; s++) {
            const int kb = s * 32;
            uint32_t ah[2][4], al[2][4];
            #pragma unroll
            for (int mi = 0; mi < 2; mi++) {
                uint32_t ra = st + (wM + mi * 16 + aRowSel) * kRowB + kb + aColSel;
                ldsm_x4(ah[mi][0], ah[mi][1], ah[mi][2], ah[mi][3], ra);
                ldsm_x4(al[mi][0], al[mi][1], al[mi][2], al[mi][3], ra + kPlaneB);
            }
            #pragma unroll
            for (int njp = 0; njp < 4; njp++) {
                uint32_t rb = st + 2 * kPlaneB
                            + (wN + njp * 16 + bRowSel) * kRowB + kb + bColSel;
                uint32_t bh[4], bl[4];
                ldsm_x4(bh[0], bh[1], bh[2], bh[3], rb);
                ldsm_x4(bl[0], bl[1], bl[2], bl[3], rb + kPlaneB);
                #pragma unroll
                for (int mi = 0; mi < 2; mi++) {
                    #pragma unroll
                    for (int half = 0; half < 2; half++) {
                        float* d = acc[mi][njp * 2 + half];
                        mma16816(d, ah[mi], bh[half * 2], bh[half * 2 + 1]);
                        mma16816(d, ah[mi], bl[half * 2], bl[half * 2 + 1]);
                        mma16816(d, al[mi], bh[half * 2], bh[half * 2 + 1]);
                    }
                }
            }
        }
    }
    __syncthreads();   // protect smem before next persistent tile refill

    #pragma unroll
    for (int mi = 0; mi < 2; mi++) {
        #pragma unroll
        for (int dd = 0; dd < 2; dd++) {
            int lrow = rowBase + wM + mi * 16 + (lane >> 2) + dd * 8;
            if (lrow >= count) continue;
            int orow = list ? list[lrow] : lrow;
            #pragma unroll
            for (int nj = 0; nj < 8; nj++) {
                int n = colBase + wN + nj * 8 + (lane & 3) * 2;
                float v0 = acc[mi][nj][dd * 2 + 0] + bias[n];
                float v1 = acc[mi][nj][dd * 2 + 1] + bias[n + 1];
                if (mode == 0) {
                    *reinterpret_cast<float2*>(C + (size_t)orow * ldc + n)
                        = make_float2(v0, v1);
                } else {
                    if (mode == 1) { v0 = fmaxf(v0, 0.f); v1 = fmaxf(v1, 0.f); }
                    else           { v0 *= scale; v1 *= scale; }
                    size_t o = (size_t)orow * ldc + n;
                    uint32_t hh, ll;
                    split2(v0, v1, hh, ll);
                    *reinterpret_cast<uint32_t*>(Chi + o) = hh;
                    *reinterpret_cast<uint32_t*>(Clo + o) = ll;
                }
            }
        }
    }
}

// ---------------- GEMM wrappers (persistent tile loops) ----------------
__global__ void __launch_bounds__(256, 2) qkv_tc(const float* bq, const float* bk, const float* bv)
{
    extern __shared__ char sm[];
    const uint32_t smb = smem_u32(sm);
    for (int idx = blockIdx.x; idx < 3 * 256; idx += kPersist) {
        int z = idx >> 8;               // 256 tiles per projection
        int rem = idx & 255;
        int ty = rem >> 3, tx = rem & 7;
        const __nv_bfloat16* bh = g_w4t_h + (size_t)z * kD * kD;
        const __nv_bfloat16* bl = g_w4t_l + (size_t)z * kD * kD;
        __nv_bfloat16* ch = (z == 0) ? g_qb_h : (z == 1) ? g_kb_h : g_vb_h;
        __nv_bfloat16* cl = (z == 0) ? g_qb_l : (z == 1) ? g_kb_l : g_vb_l;
        const float* bias = (z == 0) ? bq : (z == 1) ? bk : bv;
        float scale = (z == 0) ? 0.125f : 1.0f;
        gemm_tile(g_xb_h, g_xb_l, bh, bl, bias, kD, kNT, nullptr, 2,
                  nullptr, ch, cl, kD, scale, ty * 128, tx * 128, smb);
    }
}

__global__ void __launch_bounds__(256, 2) proj_tc(const float* bo)
{
    extern __shared__ char sm[];
    const uint32_t smb = smem_u32(sm);
    for (int idx = blockIdx.x; idx < 256; idx += kPersist) {
        int ty = idx >> 3, tx = idx & 7;
        gemm_tile(g_ab_h, g_ab_l, g_w4t_h + (size_t)3 * kD * kD,
                  g_w4t_l + (size_t)3 * kD * kD, bo, kD, kNT, nullptr, 0,
                  g_proj, nullptr, nullptr, kD, 1.f, ty * 128, tx * 128, smb);
    }
}

__global__ void __launch_bounds__(256, 2) moe1_tc(const float* b1e)
{
    extern __shared__ char sm[];
    const uint32_t smb = smem_u32(sm);
    for (int idx = blockIdx.x; ; idx += kPersist) {
        int rem = idx, e = 0, nty = 0;
        bool found = false;
        #pragma unroll
        for (e = 0; e < kE; e++) {
            nty = (g_cnt[e] + 127) >> 7;
            int tot = nty * (kFF / 128);
            if (rem < tot) { found = true; break; }
            rem -= tot;
        }
        if (!found) break;
        int ty = rem >> 5, tx = rem & 31;
        gemm_tile(g_x1b_h, g_x1b_l,
                  g_w1t_h + (size_t)e * kFF * kD, g_w1t_l + (size_t)e * kFF * kD,
                  b1e + (size_t)e * kFF, kD, g_cnt[e], g_list + e * kNT,
                  1, nullptr, g_hb_h, g_hb_l, kFF, 1.f, ty * 128, tx * 128, smb);
    }
}

__global__ void __launch_bounds__(256, 2) moe2_tc(const float* b2e)
{
    extern __shared__ char sm[];
    const uint32_t smb = smem_u32(sm);
    for (int idx = blockIdx.x; ; idx += kPersist) {
        int rem = idx, e = 0, nty = 0;
        bool found = false;
        #pragma unroll
        for (e = 0; e < kE; e++) {
            nty = (g_cnt[e] + 127) >> 7;
            int tot = nty * (kD / 128);
            if (rem < tot) { found = true; break; }
            rem -= tot;
        }
        if (!found) break;
        int ty = rem >> 3, tx = rem & 7;
        gemm_tile(g_hb_h, g_hb_l,
                  g_w2t_h + (size_t)e * kFF * kD, g_w2t_l + (size_t)e * kFF * kD,
                  b2e + (size_t)e * kD, kFF, g_cnt[e], g_list + e * kNT,
                  0, g_y, nullptr, nullptr, kD, 1.f, ty * 128, tx * 128, smb);
    }
}

// ==================== HMMA flash attention (causal, split bf16) ====================
// Q pre-scaled by 0.125 in qkv epilogue. q-tile 128 (8 warps x m16), kv-tile 64.
constexpr int kARS    = 144;                   // padded row bytes (64 bf16 + 8 pad)
constexpr int kAPlane = 64 * kARS;             // 9216
constexpr int kAStage = 4 * kAPlane;           // Kh Kl Vh Vl = 36864
constexpr int ATTN_SMEM = 2 * kAStage;         // 73728

__device__ __forceinline__ void fill_kv(uint32_t dst, int b, int h, int kbase)
{
    const __nv_bfloat16* srcs[4] = {g_kb_h, g_kb_l, g_vb_h, g_vb_l};
    #pragma unroll
    for (int i = 0; i < 8; i++) {
        int lin = threadIdx.x + 256 * i;
        int ch = lin & 7, row = (lin >> 3) & 63, pl = lin >> 9;
        const __nv_bfloat16* src = srcs[pl]
            + ((size_t)(b * kT + kbase + row) * kD + h * 64 + ch * 8);
        cp_async16(dst + pl * kAPlane + row * kARS + ch * 16, src, 16);
    }
}

__global__ void __launch_bounds__(256) attn_tc()
{
    extern __shared__ char sa[];
    const uint32_t smb = smem_u32(sa);
    const int tid = threadIdx.x, wid = tid >> 5, lane = tid & 31;
    const int qt = gridDim.x - 1 - blockIdx.x;   // longest-first launch order
    const int bh = blockIdx.y;
    const int b = bh >> 4, h = bh & 15;
    const int qb = qt * 128;
    const int wr0 = qb + wid * 16;               // warp's first q row

    // ---- load Q tile (128 x 64, hi/lo) into stage1 region ----
    #pragma unroll
    for (int i = 0; i < 8; i++) {
        int lin = tid + 256 * i;
        int ch = lin & 7, row = (lin >> 3) & 127, pl = lin >> 10;
        const __nv_bfloat16* src = (pl ? g_qb_l : g_qb_h)
            + ((size_t)(b * kT + qb + row) * kD + h * 64 + ch * 8);
        cp_async16(smb + kAStage + pl * (128 * kARS) + row * kARS + ch * 16, src, 16);
    }
    CP_COMMIT();
    fill_kv(smb, b, h, 0);
    CP_COMMIT();
    CP_WAIT(0);
    __syncthreads();

    // ---- Q fragments to registers ----
    uint32_t qh[4][4], ql[4][4];
    #pragma unroll
    for (int ks = 0; ks < 4; ks++) {
        uint32_t addr = smb + kAStage + (wid * 16 + (lane & 15)) * kARS
                      + ks * 32 + (lane >> 4) * 16;
        ldsm_x4(qh[ks][0], qh[ks][1], qh[ks][2], qh[ks][3], addr);
        ldsm_x4(ql[ks][0], ql[ks][1], ql[ks][2], ql[ks][3], addr + 128 * kARS);
    }

    float m0 = -1e30f, m1 = -1e30f, l0 = 0.f, l1 = 0.f;
    float o[8][4];
    #pragma unroll
    for (int g = 0; g < 8; g++)
        #pragma unroll
        for (int d = 0; d < 4; d++) o[g][d] = 0.f;

    const int ktmax = 2 * qt + 2;
    for (int kt = 0; kt < ktmax; kt++) {
        CP_WAIT(0);
        __syncthreads();
        if (kt + 1 < ktmax) {
            fill_kv(smb + ((kt + 1) & 1) * kAStage, b, h, (kt + 1) * 64);
            CP_COMMIT();
        }

        const int kbase = kt * 64;
        if (kbase <= wr0 + 15) {
            const uint32_t st = smb + (kt & 1) * kAStage;

            // ---- S = Q K^T (3-pass) ----
            float s[8][4];
            #pragma unroll
            for (int j = 0; j < 8; j++)
                #pragma unroll
                for (int d = 0; d < 4; d++) s[j][d] = 0.f;

            #pragma unroll
            for (int ks = 0; ks < 4; ks++) {
                #pragma unroll
                for (int ng = 0; ng < 4; ng++) {
                    uint32_t a = st + (ng * 16 + (lane & 7) + (lane >> 4) * 8) * kARS
                               + ks * 32 + ((lane >> 3) & 1) * 16;
                    uint32_t k0, k1, k2, k3, e0, e1, e2, e3;
                    ldsm_x4(k0, k1, k2, k3, a);
                    ldsm_x4(e0, e1, e2, e3, a + kAPlane);
                    mma16816(s[2*ng],   qh[ks], k0, k1);
                    mma16816(s[2*ng],   qh[ks], e0, e1);
                    mma16816(s[2*ng],   ql[ks], k0, k1);
                    mma16816(s[2*ng+1], qh[ks], k2, k3);
                    mma16816(s[2*ng+1], qh[ks], e2, e3);
                    mma16816(s[2*ng+1], ql[ks], k2, k3);
                }
            }

            // ---- mask (straddling tiles only) ----
            const int r0 = wr0 + (lane >> 2), r1 = r0 + 8;
            if (kbase + 63 > wr0) {
                #pragma unroll
                for (int j = 0; j < 8; j++) {
                    int c = kbase + j * 8 + (lane & 3) * 2;
                    if (c > r0)     s[j][0] = -1e30f;
                    if (c + 1 > r0) s[j][1] = -1e30f;
                    if (c > r1)     s[j][2] = -1e30f;
                    if (c + 1 > r1) s[j][3] = -1e30f;
                }
            }

            // ---- online softmax ----
            float rm0 = -1e30f, rm1 = -1e30f;
            #pragma unroll
            for (int j = 0; j < 8; j++) {
                rm0 = fmaxf(rm0, fmaxf(s[j][0], s[j][1]));
                rm1 = fmaxf(rm1, fmaxf(s[j][2], s[j][3]));
            }
            rm0 = fmaxf(rm0, __shfl_xor_sync(0xffffffffu, rm0, 1));
            rm0 = fmaxf(rm0, __shfl_xor_sync(0xffffffffu, rm0, 2));
            rm1 = fmaxf(rm1, __shfl_xor_sync(0xffffffffu, rm1, 1));
            rm1 = fmaxf(rm1, __shfl_xor_sync(0xffffffffu, rm1, 2));
            float mn0 = fmaxf(m0, rm0), mn1 = fmaxf(m1, rm1);
            float cr0 = __expf(m0 - mn0), cr1 = __expf(m1 - mn1);
            m0 = mn0; m1 = mn1;
            float ps0 = 0.f, ps1 = 0.f;
            #pragma unroll
            for (int j = 0; j < 8; j++) {
                s[j][0] = __expf(s[j][0] - m0);
                s[j][1] = __expf(s[j][1] - m0);
                s[j][2] = __expf(s[j][2] - m1);
                s[j][3] = __expf(s[j][3] - m1);
                ps0 += s[j][0] + s[j][1];
                ps1 += s[j][2] + s[j][3];
            }
            ps0 += __shfl_xor_sync(0xffffffffu, ps0, 1);
            ps0 += __shfl_xor_sync(0xffffffffu, ps0, 2);
            ps1 += __shfl_xor_sync(0xffffffffu, ps1, 1);
            ps1 += __shfl_xor_sync(0xffffffffu, ps1, 2);
            l0 = l0 * cr0 + ps0;
            l1 = l1 * cr1 + ps1;
            #pragma unroll
            for (int g = 0; g < 8; g++) {
                o[g][0] *= cr0; o[g][1] *= cr0;
                o[g][2] *= cr1; o[g][3] *= cr1;
            }

            // ---- O += P V (3-pass, P repacked in registers) ----
            #pragma unroll
            for (int t = 0; t < 4; t++) {
                uint32_t ph[4], pl[4];
                split2(s[2*t][0],   s[2*t][1],   ph[0], pl[0]);
                split2(s[2*t][2],   s[2*t][3],   ph[1], pl[1]);
                split2(s[2*t+1][0], s[2*t+1][1], ph[2], pl[2]);
                split2(s[2*t+1][2], s[2*t+1][3], ph[3], pl[3]);
                #pragma unroll
                for (int dg = 0; dg < 4; dg++) {
                    uint32_t a = st + 2 * kAPlane
                               + (t * 16 + (lane & 7) + ((lane >> 3) & 1) * 8) * kARS
                               + dg * 32 + (lane >> 4) * 16;
                    uint32_t v0, v1, v2, v3, w0, w1, w2, w3;
                    ldsm_x4_t(v0, v1, v2, v3, a);
                    ldsm_x4_t(w0, w1, w2, w3, a + kAPlane);
                    mma16816(o[2*dg],   ph, v0, v1);
                    mma16816(o[2*dg],   ph, w0, w1);
                    mma16816(o[2*dg],   pl, v0, v1);
                    mma16816(o[2*dg+1], ph, v2, v3);
                    mma16816(o[2*dg+1], ph, w2, w3);
                    mma16816(o[2*dg+1], pl, v2, v3);
                }
            }
        }
    }

    // ---- epilogue: O/l -> bf16 hi/lo planes ----
    const float inv0 = 1.f / l0, inv1 = 1.f / l1;
    const size_t tok0 = (size_t)(b * kT) + wr0 + (lane >> 2);
    #pragma unroll
    for (int g = 0; g < 8; g++) {
        int col = h * 64 + g * 8 + (lane & 3) * 2;
        uint32_t hh, ll;
        split2(o[g][0] * inv0, o[g][1] * inv0, hh, ll);
        *reinterpret_cast<uint32_t*>(g_ab_h + tok0 * kD + col) = hh;
        *reinterpret_cast<uint32_t*>(g_ab_l + tok0 * kD + col) = ll;
        split2(o[g][2] * inv1, o[g][3] * inv1, hh, ll);
        *reinterpret_cast<uint32_t*>(g_ab_h + (tok0 + 8) * kD + col) = hh;
        *reinterpret_cast<uint32_t*>(g_ab_l + (tok0 + 8) * kD + col) = ll;
    }
}

// ---------------- conversion kernels ----------------
__global__ void convert_x(const float* __restrict__ x)
{
    int i = blockIdx.x * 256 + threadIdx.x;
    float4 v = ((const float4*)x)[i];
    size_t o = (size_t)i * 4;
    float a[4] = {v.x, v.y, v.z, v.w};
    #pragma unroll
    for (int j = 0; j < 4; j++) {
        __nv_bfloat16 h = __float2bfloat16_rn(a[j]);
        g_xb_h[o + j] = h;
        g_xb_l[o + j] = __float2bfloat16_rn(a[j] - __bfloat162float(h));
    }
}

__device__ __forceinline__ void transpose_body(
    const float* __restrict__ src, __nv_bfloat16* __restrict__ hi,
    __nv_bfloat16* __restrict__ lo, int K, int N)
{
    __shared__ float tile[32][33];
    int bn = blockIdx.x * 32, bk = blockIdx.y * 32;
    int tx = threadIdx.x, ty = threadIdx.y;
    #pragma unroll
    for (int i = 0; i < 32; i += 8)
        tile[ty + i][tx] = src[(size_t)(bk + ty + i) * N + bn + tx];
    __syncthreads();
    #pragma unroll
    for (int i = 0; i < 32; i += 8) {
        float v = tile[tx][ty + i];
        __nv_bfloat16 h = __float2bfloat16_rn(v);
        size_t o = (size_t)(bn + ty + i) * K + bk + tx;
        hi[o] = h;
        lo[o] = __float2bfloat16_rn(v - __bfloat162float(h));
    }
}

__global__ void transpose_qkvo(const float* Wq, const float* Wk, const float* Wv, const float* Wo)
{
    int z = blockIdx.z;
    const float* src = (z == 0) ? Wq : (z == 1) ? Wk : (z == 2) ? Wv : Wo;
    transpose_body(src, g_w4t_h + (size_t)z * kD * kD, g_w4t_l + (size_t)z * kD * kD, kD, kD);
}

__global__ void transpose_w1(const float* W1e)
{
    int e = blockIdx.z;
    size_t off = (size_t)e * kD * kFF;
    transpose_body(W1e + off, g_w1t_h + off, g_w1t_l + off, kD, kFF);
}

__global__ void transpose_w2(const float* W2e)
{
    int e = blockIdx.z;
    size_t off = (size_t)e * kFF * kD;
    transpose_body(W2e + off, g_w2t_h + off, g_w2t_l + off, kFF, kD);
}

// ---------------- add + layernorm ----------------
__device__ __forceinline__ float block_sum_256(float v, float* red)
{
    int tid = threadIdx.x;
    #pragma unroll
    for (int o = 16; o; o >>= 1) v += __shfl_xor_sync(0xffffffffu, v, o);
    if ((tid & 31) == 0) red[tid >> 5] = v;
    __syncthreads();
    if (tid < 8) {
        float x = red[tid];
        #pragma unroll
        for (int o = 4; o; o >>= 1) x += __shfl_xor_sync(0xffu, x, o);
        if (tid == 0) red[0] = x;
    }
    __syncthreads();
    float r = red[0];
    __syncthreads();
    return r;
}

__device__ __forceinline__ void add_ln_body(
    const float* __restrict__ A, const float* __restrict__ Bb,
    const float* __restrict__ gw, const float* __restrict__ bw,
    float* __restrict__ out, __nv_bfloat16* __restrict__ oh,
    __nv_bfloat16* __restrict__ ol)
{
    __shared__ float red[8];
    int t = blockIdx.x, tid = threadIdx.x;
    float4 av = ((const float4*)(A  + (size_t)t * kD))[tid];
    float4 bv = ((const float4*)(Bb + (size_t)t * kD))[tid];
    float vx = av.x + bv.x, vy = av.y + bv.y, vz = av.z + bv.z, vw = av.w + bv.w;
    float ssum = block_sum_256(vx + vy + vz + vw, red);
    float mu = ssum * (1.0f / kD);
    float dx = vx - mu, dy = vy - mu, dz = vz - mu, dw = vw - mu;
    float sq = block_sum_256(dx*dx + dy*dy + dz*dz + dw*dw, red);
    float rstd = rsqrtf(sq * (1.0f / kD) + kEPS);
    float4 gv = ((const float4*)gw)[tid];
    float4 be = ((const float4*)bw)[tid];
    float ovv[4] = {dx*rstd*gv.x + be.x, dy*rstd*gv.y + be.y,
                    dz*rstd*gv.z + be.z, dw*rstd*gv.w + be.w};
    ((float4*)(out + (size_t)t * kD))[tid] = make_float4(ovv[0], ovv[1], ovv[2], ovv[3]);
    if (oh) {
        size_t o = (size_t)t * kD + tid * 4;
        #pragma unroll
        for (int j = 0; j < 4; j++) {
            __nv_bfloat16 h = __float2bfloat16_rn(ovv[j]);
            oh[o + j] = h;
            ol[o + j] = __float2bfloat16_rn(ovv[j] - __bfloat162float(h));
        }
    }
}

__global__ void ln1_kernel(const float* __restrict__ x,
                           const float* __restrict__ g, const float* __restrict__ b)
{
    add_ln_body(x, g_proj, g, b, g_x1, g_x1b_h, g_x1b_l);
}

__global__ void ln2_kernel(const float* __restrict__ g, const float* __restrict__ b,
                           float* __restrict__ out)
{
    add_ln_body(g_x1, g_y, g, b, out, nullptr, nullptr);
}

// ---------------- MoE gate (top-1 argmax) ----------------
__global__ void zero_cnt()
{
    if (threadIdx.x < kE) g_cnt[threadIdx.x] = 0;
}

__global__ void gate_kernel(const float* __restrict__ Wg, const float* __restrict__ bg)
{
    int t = blockIdx.x, tid = threadIdx.x;
    float a0 = 0.f, a1 = 0.f, a2 = 0.f, a3 = 0.f;
    const float* xr = g_x1 + (size_t)t * kD;
    for (int d = tid; d < kD; d += 128) {
        float xv = xr[d];
        float4 w = ((const float4*)Wg)[d];
        a0 = fmaf(xv, w.x, a0);
        a1 = fmaf(xv, w.y, a1);
        a2 = fmaf(xv, w.z, a2);
        a3 = fmaf(xv, w.w, a3);
    }
    __shared__ float rsm[4][128];
    rsm[0][tid] = a0; rsm[1][tid] = a1; rsm[2][tid] = a2; rsm[3][tid] = a3;
    __syncthreads();
    for (int s = 64; s > 0; s >>= 1) {
        if (tid < s) {
            #pragma unroll
            for (int e = 0; e < 4; e++) rsm[e][tid] += rsm[e][tid + s];
        }
        __syncthreads();
    }
    if (tid == 0) {
        float sc[4];
        #pragma unroll
        for (int e = 0; e < 4; e++) sc[e] = rsm[e][0] + bg[e];
        int best = 0; float bvv = sc[0];
        #pragma unroll
        for (int e = 1; e < 4; e++) {
            if (sc[e] > bvv) { bvv = sc[e]; best = e; }
        }
        int pos = atomicAdd(&g_cnt[best], 1);
        g_list[best * kNT + pos] = t;
    }
}

// ---------------- launch ----------------
extern "C" void kernel_launch(void* const* d_in, const int* in_sizes, int n_in,
                              void* d_out, int out_size)
{
    const float* x    = (const float*)d_in[0];
    const float* Wq   = (const float*)d_in[2];
    const float* bq   = (const float*)d_in[3];
    const float* Wk   = (const float*)d_in[4];
    const float* bk   = (const float*)d_in[5];
    const float* Wv   = (const float*)d_in[6];
    const float* bv   = (const float*)d_in[7];
    const float* Wo   = (const float*)d_in[8];
    const float* bo   = (const float*)d_in[9];
    const float* ln1g = (const float*)d_in[10];
    const float* ln1b = (const float*)d_in[11];
    const float* Wg   = (const float*)d_in[12];
    const float* bg   = (const float*)d_in[13];
    const float* W1e  = (const float*)d_in[14];
    const float* b1e  = (const float*)d_in[15];
    const float* W2e  = (const float*)d_in[16];
    const float* b2e  = (const float*)d_in[17];
    const float* ln2g = (const float*)d_in[18];
    const float* ln2b = (const float*)d_in[19];
    float* out = (float*)d_out;

    cudaFuncSetAttribute(attn_tc, cudaFuncAttributeMaxDynamicSharedMemorySize, ATTN_SMEM);
    cudaFuncSetAttribute(qkv_tc,  cudaFuncAttributeMaxDynamicSharedMemorySize, GEMM_SMEM);
    cudaFuncSetAttribute(proj_tc, cudaFuncAttributeMaxDynamicSharedMemorySize, GEMM_SMEM);
    cudaFuncSetAttribute(moe1_tc, cudaFuncAttributeMaxDynamicSharedMemorySize, GEMM_SMEM);
    cudaFuncSetAttribute(moe2_tc, cudaFuncAttributeMaxDynamicSharedMemorySize, GEMM_SMEM);

    // side stream for prep work that can overlap the main chain
    cudaStream_t side;
    cudaEvent_t evFork, evJoin1, evJoin2;
    cudaStreamCreateWithFlags(&side, cudaStreamNonBlocking);
    cudaEventCreateWithFlags(&evFork, cudaEventDisableTiming);
    cudaEventCreateWithFlags(&evJoin1, cudaEventDisableTiming);
    cudaEventCreateWithFlags(&evJoin2, cudaEventDisableTiming);

    cudaEventRecord(evFork, 0);
    cudaStreamWaitEvent(side, evFork, 0);
    convert_x<<<kNT * kD / 4 / 256, 256, 0, side>>>(x);
    cudaEventRecord(evJoin1, side);
    transpose_w1<<<dim3(kFF/32, kD/32, kE), dim3(32, 8), 0, side>>>(W1e);
    transpose_w2<<<dim3(kD/32, kFF/32, kE), dim3(32, 8), 0, side>>>(W2e);
    cudaEventRecord(evJoin2, side);

    // main chain: attention path
    transpose_qkvo<<<dim3(kD/32, kD/32, 4), dim3(32, 8)>>>(Wq, Wk, Wv, Wo);
    cudaStreamWaitEvent(0, evJoin1, 0);
    qkv_tc<<<kPersist, 256, GEMM_SMEM>>>(bq, bk, bv);
    attn_tc<<<dim3(kT/128, kB*kH), 256, ATTN_SMEM>>>();
    proj_tc<<<kPersist, 256, GEMM_SMEM>>>(bo);
    ln1_kernel<<<kNT, 256>>>(x, ln1g, ln1b);

    // MoE path
    zero_cnt<<<1, 32>>>();
    gate_kernel<<<kNT, 128>>>(Wg, bg);
    cudaStreamWaitEvent(0, evJoin2, 0);
    moe1_tc<<<kPersist, 256, GEMM_SMEM>>>(b1e);
    moe2_tc<<<kPersist, 256, GEMM_SMEM>>>(b2e);
    ln2_kernel<<<kNT, 256>>>(ln2g, ln2b, out);
}

// round 8
// speedup vs baseline: 1.0349x; 1.0349x over previous
#include <cuda_runtime.h>
#include <cuda_bf16.h>
#include <math.h>
#include <stdint.h>

// ---------------- problem constants ----------------
constexpr int kB  = 2;
constexpr int kT  = 2048;
constexpr int kD  = 1024;
constexpr int kH  = 16;
constexpr int kDH = 64;
constexpr int kFF = 4096;
constexpr int kE  = 4;
constexpr int kNT = kB * kT;           // 4096 tokens
constexpr float kEPS = 1e-5f;

// ---------------- scratch (device globals: allocation-free) ----------------
__device__ float g_proj[kNT * kD];
__device__ float g_x1[kNT * kD];
__device__ float g_y[kNT * kD];
__device__ int   g_cnt[kE];
__device__ int   g_list[kE * kNT];

// bf16 hi/lo planes (activations)
__device__ __nv_bfloat16 g_xb_h[kNT * kD],  g_xb_l[kNT * kD];
__device__ __nv_bfloat16 g_qb_h[kNT * kD],  g_qb_l[kNT * kD];
__device__ __nv_bfloat16 g_kb_h[kNT * kD],  g_kb_l[kNT * kD];
__device__ __nv_bfloat16 g_vb_h[kNT * kD],  g_vb_l[kNT * kD];
__device__ __nv_bfloat16 g_ab_h[kNT * kD],  g_ab_l[kNT * kD];     // attn out
__device__ __nv_bfloat16 g_x1b_h[kNT * kD], g_x1b_l[kNT * kD];
__device__ __nv_bfloat16 g_hb_h[(size_t)kNT * kFF], g_hb_l[(size_t)kNT * kFF];

// bf16 hi/lo planes (transposed weights, [N][K] K-major)
__device__ __nv_bfloat16 g_w4t_h[4 * kD * kD], g_w4t_l[4 * kD * kD];   // Wq,Wk,Wv,Wo
__device__ __nv_bfloat16 g_w1t_h[(size_t)kE * kFF * kD], g_w1t_l[(size_t)kE * kFF * kD];
__device__ __nv_bfloat16 g_w2t_h[(size_t)kE * kFF * kD], g_w2t_l[(size_t)kE * kFF * kD];

// ==================== PTX helpers (base sm_103 features only) ====================
__device__ __forceinline__ uint32_t smem_u32(const void* p) {
    uint32_t a;
    asm("{ .reg .u64 t; cvta.to.shared.u64 t, %1; cvt.u32.u64 %0, t; }" : "=r"(a) : "l"(p));
    return a;
}

__device__ __forceinline__ void cp_async16(uint32_t s, const void* g, int sz) {
    asm volatile("cp.async.cg.shared.global [%0], [%1], 16, %2;"
                 :: "r"(s), "l"(g), "r"(sz) : "memory");
}
#define CP_COMMIT()  asm volatile("cp.async.commit_group;" ::: "memory")
#define CP_WAIT(n)   asm volatile("cp.async.wait_group %0;" :: "n"(n) : "memory")

__device__ __forceinline__ void ldsm_x4(uint32_t& r0, uint32_t& r1, uint32_t& r2,
                                        uint32_t& r3, uint32_t addr) {
    asm volatile("ldmatrix.sync.aligned.m8n8.x4.shared.b16 {%0,%1,%2,%3}, [%4];"
                 : "=r"(r0), "=r"(r1), "=r"(r2), "=r"(r3) : "r"(addr));
}
__device__ __forceinline__ void ldsm_x4_t(uint32_t& r0, uint32_t& r1, uint32_t& r2,
                                          uint32_t& r3, uint32_t addr) {
    asm volatile("ldmatrix.sync.aligned.m8n8.x4.trans.shared.b16 {%0,%1,%2,%3}, [%4];"
                 : "=r"(r0), "=r"(r1), "=r"(r2), "=r"(r3) : "r"(addr));
}

__device__ __forceinline__ void mma16816(float* d, const uint32_t* a,
                                         uint32_t b0, uint32_t b1) {
    asm volatile("mma.sync.aligned.m16n8k16.row.col.f32.bf16.bf16.f32 "
                 "{%0,%1,%2,%3}, {%4,%5,%6,%7}, {%8,%9}, {%0,%1,%2,%3};"
                 : "+f"(d[0]), "+f"(d[1]), "+f"(d[2]), "+f"(d[3])
                 : "r"(a[0]), "r"(a[1]), "r"(a[2]), "r"(a[3]), "r"(b0), "r"(b1));
}

// split (f0,f1) into packed bf16 hi and lo planes
__device__ __forceinline__ void split2(float f0, float f1, uint32_t& h, uint32_t& l) {
    __nv_bfloat162 hv = __floats2bfloat162_rn(f0, f1);
    float r0 = f0 - __bfloat162float(hv.x);
    float r1 = f1 - __bfloat162float(hv.y);
    __nv_bfloat162 lv = __floats2bfloat162_rn(r0, r1);
    h = *reinterpret_cast<uint32_t*>(&hv);
    l = *reinterpret_cast<uint32_t*>(&lv);
}

// ==================== mma.sync split-bf16 GEMM ====================
// Block 128x128, 256 threads (8 warps, 4Mx2N), warp tile 32x64, K-chunk 32.
constexpr int kRowB   = 80;                    // padded row bytes (32 bf16 + 8 pad)
constexpr int kPlaneB = 128 * kRowB;           // 10240
constexpr int kStageB = 4 * kPlaneB;           // Ah Al Bh Bl = 40960
constexpr int GEMM_SMEM = 2 * kStageB;         // 81920

struct GemmPtrs {
    const __nv_bfloat16 *aH0, *aL0, *aH1, *aL1;
    const __nv_bfloat16 *bH0, *bL0, *bH1, *bL1;
    int v0, v1, c8;
};

__device__ __forceinline__ void fill_stage(uint32_t sb, int k0, const GemmPtrs& P)
{
    int o = (threadIdx.x >> 2) * kRowB + (threadIdx.x & 3) * 16;
    int g = k0 + P.c8;
    cp_async16(sb + o,                       P.aH0 + g, P.v0 ? 16 : 0);
    cp_async16(sb + o + 64 * kRowB,          P.aH1 + g, P.v1 ? 16 : 0);
    cp_async16(sb + kPlaneB + o,             P.aL0 + g, P.v0 ? 16 : 0);
    cp_async16(sb + kPlaneB + o + 64*kRowB,  P.aL1 + g, P.v1 ? 16 : 0);
    cp_async16(sb + 2*kPlaneB + o,           P.bH0 + g, 16);
    cp_async16(sb + 2*kPlaneB + o + 64*kRowB,P.bH1 + g, 16);
    cp_async16(sb + 3*kPlaneB + o,           P.bL0 + g, 16);
    cp_async16(sb + 3*kPlaneB + o + 64*kRowB,P.bL1 + g, 16);
}

// mode 0: C = acc + bias (fp32)
// mode 1: relu(acc+bias) -> Chi/Clo bf16 planes
// mode 2: (acc+bias)*scale -> Chi/Clo bf16 planes
__device__ __forceinline__ void gemm_tc(
    const __nv_bfloat16* __restrict__ Ah, const __nv_bfloat16* __restrict__ Al,
    const __nv_bfloat16* __restrict__ Bh, const __nv_bfloat16* __restrict__ Bl,
    const float* __restrict__ bias, int K, int count, const int* __restrict__ list,
    int mode, float* __restrict__ C,
    __nv_bfloat16* __restrict__ Chi, __nv_bfloat16* __restrict__ Clo, int ldc,
    float scale)
{
    extern __shared__ char sm[];
    const int tid  = threadIdx.x;
    const int wid  = tid >> 5, lane = tid & 31;
    const int rowBase = blockIdx.y * 128;
    const int colBase = blockIdx.x * 128;
    if (rowBase >= count) return;

    GemmPtrs P;
    {
        int r0 = tid >> 2;
        int gr0 = rowBase + r0, gr1 = rowBase + r0 + 64;
        P.v0 = gr0 < count;
        P.v1 = gr1 < count;
        int rr0 = P.v0 ? (list ? list[gr0] : gr0) : 0;
        int rr1 = P.v1 ? (list ? list[gr1] : gr1) : 0;
        P.aH0 = Ah + (size_t)rr0 * K;  P.aL0 = Al + (size_t)rr0 * K;
        P.aH1 = Ah + (size_t)rr1 * K;  P.aL1 = Al + (size_t)rr1 * K;
        P.bH0 = Bh + (size_t)(colBase + r0) * K;
        P.bH1 = Bh + (size_t)(colBase + r0 + 64) * K;
        P.bL0 = Bl + (size_t)(colBase + r0) * K;
        P.bL1 = Bl + (size_t)(colBase + r0 + 64) * K;
        P.c8  = (tid & 3) * 8;
    }
    const uint32_t smb = smem_u32(sm);

    const int wM = (wid & 3) * 32;
    const int wN = (wid >> 2) * 64;

    float acc[2][8][4];
    #pragma unroll
    for (int i = 0; i < 2; i++)
        #pragma unroll
        for (int j = 0; j < 8; j++)
            #pragma unroll
            for (int d = 0; d < 4; d++) acc[i][j][d] = 0.f;

    const int nc = K / 32;
    fill_stage(smb, 0, P);
    CP_COMMIT();

    const int aRowSel = lane & 15, aColSel = (lane >> 4) * 16;
    const int bRowSel = (lane & 7) + ((lane >> 4) & 1) * 8;
    const int bColSel = ((lane >> 3) & 1) * 16;

    for (int c = 0; c < nc; c++) {
        CP_WAIT(0);
        __syncthreads();
        if (c + 1 < nc) {
            fill_stage(smb + ((c + 1) & 1) * kStageB, (c + 1) * 32, P);
            CP_COMMIT();
        }

        uint32_t st = smb + (c & 1) * kStageB;
        #pragma unroll
        for (int s = 0; s < 2; s++) {
            const int kb = s * 32;
            uint32_t ah[2][4], al[2][4];
            #pragma unroll
            for (int mi = 0; mi < 2; mi++) {
                uint32_t ra = st + (wM + mi * 16 + aRowSel) * kRowB + kb + aColSel;
                ldsm_x4(ah[mi][0], ah[mi][1], ah[mi][2], ah[mi][3], ra);
                ldsm_x4(al[mi][0], al[mi][1], al[mi][2], al[mi][3], ra + kPlaneB);
            }
            #pragma unroll
            for (int njp = 0; njp < 4; njp++) {
                uint32_t rb = st + 2 * kPlaneB
                            + (wN + njp * 16 + bRowSel) * kRowB + kb + bColSel;
                uint32_t bh[4], bl[4];
                ldsm_x4(bh[0], bh[1], bh[2], bh[3], rb);
                ldsm_x4(bl[0], bl[1], bl[2], bl[3], rb + kPlaneB);
                #pragma unroll
                for (int mi = 0; mi < 2; mi++) {
                    #pragma unroll
                    for (int half = 0; half < 2; half++) {
                        float* d = acc[mi][njp * 2 + half];
                        mma16816(d, ah[mi], bh[half * 2], bh[half * 2 + 1]);
                        mma16816(d, ah[mi], bl[half * 2], bl[half * 2 + 1]);
                        mma16816(d, al[mi], bh[half * 2], bh[half * 2 + 1]);
                    }
                }
            }
        }
    }

    #pragma unroll
    for (int mi = 0; mi < 2; mi++) {
        #pragma unroll
        for (int dd = 0; dd < 2; dd++) {
            int lrow = rowBase + wM + mi * 16 + (lane >> 2) + dd * 8;
            if (lrow >= count) continue;
            int orow = list ? list[lrow] : lrow;
            #pragma unroll
            for (int nj = 0; nj < 8; nj++) {
                int n = colBase + wN + nj * 8 + (lane & 3) * 2;
                float v0 = acc[mi][nj][dd * 2 + 0] + bias[n];
                float v1 = acc[mi][nj][dd * 2 + 1] + bias[n + 1];
                if (mode == 0) {
                    *reinterpret_cast<float2*>(C + (size_t)orow * ldc + n)
                        = make_float2(v0, v1);
                } else {
                    if (mode == 1) { v0 = fmaxf(v0, 0.f); v1 = fmaxf(v1, 0.f); }
                    else           { v0 *= scale; v1 *= scale; }
                    size_t o = (size_t)orow * ldc + n;
                    uint32_t hh, ll;
                    split2(v0, v1, hh, ll);
                    *reinterpret_cast<uint32_t*>(Chi + o) = hh;
                    *reinterpret_cast<uint32_t*>(Clo + o) = ll;
                }
            }
        }
    }
}

// ---------------- GEMM wrappers ----------------
__global__ void __launch_bounds__(256, 2) qkv_tc(const float* bq, const float* bk, const float* bv)
{
    int z = blockIdx.z;
    const __nv_bfloat16* bh = g_w4t_h + (size_t)z * kD * kD;
    const __nv_bfloat16* bl = g_w4t_l + (size_t)z * kD * kD;
    __nv_bfloat16* ch = (z == 0) ? g_qb_h : (z == 1) ? g_kb_h : g_vb_h;
    __nv_bfloat16* cl = (z == 0) ? g_qb_l : (z == 1) ? g_kb_l : g_vb_l;
    const float* bias = (z == 0) ? bq : (z == 1) ? bk : bv;
    float scale = (z == 0) ? 0.125f : 1.0f;
    gemm_tc(g_xb_h, g_xb_l, bh, bl, bias, kD, kNT, nullptr, 2, nullptr, ch, cl, kD, scale);
}

__global__ void __launch_bounds__(256, 2) proj_tc(const float* bo)
{
    gemm_tc(g_ab_h, g_ab_l, g_w4t_h + (size_t)3 * kD * kD, g_w4t_l + (size_t)3 * kD * kD,
            bo, kD, kNT, nullptr, 0, g_proj, nullptr, nullptr, kD, 1.f);
}

__global__ void __launch_bounds__(256, 2) moe1_tc(const float* b1e)
{
    int e = blockIdx.z;
    int cnt = g_cnt[e];
    gemm_tc(g_x1b_h, g_x1b_l,
            g_w1t_h + (size_t)e * kFF * kD, g_w1t_l + (size_t)e * kFF * kD,
            b1e + (size_t)e * kFF, kD, cnt, g_list + e * kNT,
            1, nullptr, g_hb_h, g_hb_l, kFF, 1.f);
}

__global__ void __launch_bounds__(256, 2) moe2_tc(const float* b2e)
{
    int e = blockIdx.z;
    int cnt = g_cnt[e];
    gemm_tc(g_hb_h, g_hb_l,
            g_w2t_h + (size_t)e * kFF * kD, g_w2t_l + (size_t)e * kFF * kD,
            b2e + (size_t)e * kD, kFF, cnt, g_list + e * kNT,
            0, g_y, nullptr, nullptr, kD, 1.f);
}

// ==================== HMMA flash attention (causal, split bf16) ====================
// Q pre-scaled by 0.125 in qkv epilogue. q-tile 128 (8 warps x m16), kv-tile 64.
constexpr int kARS    = 144;                   // padded row bytes (64 bf16 + 8 pad)
constexpr int kAPlane = 64 * kARS;             // 9216
constexpr int kAStage = 4 * kAPlane;           // Kh Kl Vh Vl = 36864
constexpr int ATTN_SMEM = 2 * kAStage;         // 73728

__device__ __forceinline__ void fill_kv(uint32_t dst, int b, int h, int kbase)
{
    const __nv_bfloat16* srcs[4] = {g_kb_h, g_kb_l, g_vb_h, g_vb_l};
    #pragma unroll
    for (int i = 0; i < 8; i++) {
        int lin = threadIdx.x + 256 * i;
        int ch = lin & 7, row = (lin >> 3) & 63, pl = lin >> 9;
        const __nv_bfloat16* src = srcs[pl]
            + ((size_t)(b * kT + kbase + row) * kD + h * 64 + ch * 8);
        cp_async16(dst + pl * kAPlane + row * kARS + ch * 16, src, 16);
    }
}

__global__ void __launch_bounds__(256) attn_tc()
{
    extern __shared__ char sa[];
    const uint32_t smb = smem_u32(sa);
    const int tid = threadIdx.x, wid = tid >> 5, lane = tid & 31;
    const int qt = gridDim.x - 1 - blockIdx.x;   // longest-first launch order
    const int bh = blockIdx.y;
    const int b = bh >> 4, h = bh & 15;
    const int qb = qt * 128;
    const int wr0 = qb + wid * 16;               // warp's first q row

    // ---- load Q tile (128 x 64, hi/lo) into stage1 region ----
    #pragma unroll
    for (int i = 0; i < 8; i++) {
        int lin = tid + 256 * i;
        int ch = lin & 7, row = (lin >> 3) & 127, pl = lin >> 10;
        const __nv_bfloat16* src = (pl ? g_qb_l : g_qb_h)
            + ((size_t)(b * kT + qb + row) * kD + h * 64 + ch * 8);
        cp_async16(smb + kAStage + pl * (128 * kARS) + row * kARS + ch * 16, src, 16);
    }
    CP_COMMIT();
    fill_kv(smb, b, h, 0);
    CP_COMMIT();
    CP_WAIT(0);
    __syncthreads();

    // ---- Q fragments to registers ----
    uint32_t qh[4][4], ql[4][4];
    #pragma unroll
    for (int ks = 0; ks < 4; ks++) {
        uint32_t addr = smb + kAStage + (wid * 16 + (lane & 15)) * kARS
                      + ks * 32 + (lane >> 4) * 16;
        ldsm_x4(qh[ks][0], qh[ks][1], qh[ks][2], qh[ks][3], addr);
        ldsm_x4(ql[ks][0], ql[ks][1], ql[ks][2], ql[ks][3], addr + 128 * kARS);
    }

    float m0 = -1e30f, m1 = -1e30f, l0 = 0.f, l1 = 0.f;
    float o[8][4];
    #pragma unroll
    for (int g = 0; g < 8; g++)
        #pragma unroll
        for (int d = 0; d < 4; d++) o[g][d] = 0.f;

    const int ktmax = 2 * qt + 2;
    for (int kt = 0; kt < ktmax; kt++) {
        CP_WAIT(0);
        __syncthreads();
        if (kt + 1 < ktmax) {
            fill_kv(smb + ((kt + 1) & 1) * kAStage, b, h, (kt + 1) * 64);
            CP_COMMIT();
        }

        const int kbase = kt * 64;
        if (kbase <= wr0 + 15) {
            const uint32_t st = smb + (kt & 1) * kAStage;

            // ---- S = Q K^T (3-pass) ----
            float s[8][4];
            #pragma unroll
            for (int j = 0; j < 8; j++)
                #pragma unroll
                for (int d = 0; d < 4; d++) s[j][d] = 0.f;

            #pragma unroll
            for (int ks = 0; ks < 4; ks++) {
                #pragma unroll
                for (int ng = 0; ng < 4; ng++) {
                    uint32_t a = st + (ng * 16 + (lane & 7) + (lane >> 4) * 8) * kARS
                               + ks * 32 + ((lane >> 3) & 1) * 16;
                    uint32_t k0, k1, k2, k3, e0, e1, e2, e3;
                    ldsm_x4(k0, k1, k2, k3, a);
                    ldsm_x4(e0, e1, e2, e3, a + kAPlane);
                    mma16816(s[2*ng],   qh[ks], k0, k1);
                    mma16816(s[2*ng],   qh[ks], e0, e1);
                    mma16816(s[2*ng],   ql[ks], k0, k1);
                    mma16816(s[2*ng+1], qh[ks], k2, k3);
                    mma16816(s[2*ng+1], qh[ks], e2, e3);
                    mma16816(s[2*ng+1], ql[ks], k2, k3);
                }
            }

            // ---- mask (straddling tiles only) ----
            const int r0 = wr0 + (lane >> 2), r1 = r0 + 8;
            if (kbase + 63 > wr0) {
                #pragma unroll
                for (int j = 0; j < 8; j++) {
                    int c = kbase + j * 8 + (lane & 3) * 2;
                    if (c > r0)     s[j][0] = -1e30f;
                    if (c + 1 > r0) s[j][1] = -1e30f;
                    if (c > r1)     s[j][2] = -1e30f;
                    if (c + 1 > r1) s[j][3] = -1e30f;
                }
            }

            // ---- online softmax ----
            float rm0 = -1e30f, rm1 = -1e30f;
            #pragma unroll
            for (int j = 0; j < 8; j++) {
                rm0 = fmaxf(rm0, fmaxf(s[j][0], s[j][1]));
                rm1 = fmaxf(rm1, fmaxf(s[j][2], s[j][3]));
            }
            rm0 = fmaxf(rm0, __shfl_xor_sync(0xffffffffu, rm0, 1));
            rm0 = fmaxf(rm0, __shfl_xor_sync(0xffffffffu, rm0, 2));
            rm1 = fmaxf(rm1, __shfl_xor_sync(0xffffffffu, rm1, 1));
            rm1 = fmaxf(rm1, __shfl_xor_sync(0xffffffffu, rm1, 2));
            float mn0 = fmaxf(m0, rm0), mn1 = fmaxf(m1, rm1);
            float cr0 = __expf(m0 - mn0), cr1 = __expf(m1 - mn1);
            m0 = mn0; m1 = mn1;
            float ps0 = 0.f, ps1 = 0.f;
            #pragma unroll
            for (int j = 0; j < 8; j++) {
                s[j][0] = __expf(s[j][0] - m0);
                s[j][1] = __expf(s[j][1] - m0);
                s[j][2] = __expf(s[j][2] - m1);
                s[j][3] = __expf(s[j][3] - m1);
                ps0 += s[j][0] + s[j][1];
                ps1 += s[j][2] + s[j][3];
            }
            ps0 += __shfl_xor_sync(0xffffffffu, ps0, 1);
            ps0 += __shfl_xor_sync(0xffffffffu, ps0, 2);
            ps1 += __shfl_xor_sync(0xffffffffu, ps1, 1);
            ps1 += __shfl_xor_sync(0xffffffffu, ps1, 2);
            l0 = l0 * cr0 + ps0;
            l1 = l1 * cr1 + ps1;
            #pragma unroll
            for (int g = 0; g < 8; g++) {
                o[g][0] *= cr0; o[g][1] *= cr0;
                o[g][2] *= cr1; o[g][3] *= cr1;
            }

            // ---- O += P V (3-pass, P repacked in registers) ----
            #pragma unroll
            for (int t = 0; t < 4; t++) {
                uint32_t ph[4], pl[4];
                split2(s[2*t][0],   s[2*t][1],   ph[0], pl[0]);
                split2(s[2*t][2],   s[2*t][3],   ph[1], pl[1]);
                split2(s[2*t+1][0], s[2*t+1][1], ph[2], pl[2]);
                split2(s[2*t+1][2], s[2*t+1][3], ph[3], pl[3]);
                #pragma unroll
                for (int dg = 0; dg < 4; dg++) {
                    uint32_t a = st + 2 * kAPlane
                               + (t * 16 + (lane & 7) + ((lane >> 3) & 1) * 8) * kARS
                               + dg * 32 + (lane >> 4) * 16;
                    uint32_t v0, v1, v2, v3, w0, w1, w2, w3;
                    ldsm_x4_t(v0, v1, v2, v3, a);
                    ldsm_x4_t(w0, w1, w2, w3, a + kAPlane);
                    mma16816(o[2*dg],   ph, v0, v1);
                    mma16816(o[2*dg],   ph, w0, w1);
                    mma16816(o[2*dg],   pl, v0, v1);
                    mma16816(o[2*dg+1], ph, v2, v3);
                    mma16816(o[2*dg+1], ph, w2, w3);
                    mma16816(o[2*dg+1], pl, v2, v3);
                }
            }
        }
    }

    // ---- epilogue: O/l -> bf16 hi/lo planes ----
    const float inv0 = 1.f / l0, inv1 = 1.f / l1;
    const size_t tok0 = (size_t)(b * kT) + wr0 + (lane >> 2);
    #pragma unroll
    for (int g = 0; g < 8; g++) {
        int col = h * 64 + g * 8 + (lane & 3) * 2;
        uint32_t hh, ll;
        split2(o[g][0] * inv0, o[g][1] * inv0, hh, ll);
        *reinterpret_cast<uint32_t*>(g_ab_h + tok0 * kD + col) = hh;
        *reinterpret_cast<uint32_t*>(g_ab_l + tok0 * kD + col) = ll;
        split2(o[g][2] * inv1, o[g][3] * inv1, hh, ll);
        *reinterpret_cast<uint32_t*>(g_ab_h + (tok0 + 8) * kD + col) = hh;
        *reinterpret_cast<uint32_t*>(g_ab_l + (tok0 + 8) * kD + col) = ll;
    }
}

// ---------------- conversion kernels ----------------
__global__ void convert_x(const float* __restrict__ x)
{
    int i = blockIdx.x * 256 + threadIdx.x;
    float4 v = ((const float4*)x)[i];
    size_t o = (size_t)i * 4;
    float a[4] = {v.x, v.y, v.z, v.w};
    #pragma unroll
    for (int j = 0; j < 4; j++) {
        __nv_bfloat16 h = __float2bfloat16_rn(a[j]);
        g_xb_h[o + j] = h;
        g_xb_l[o + j] = __float2bfloat16_rn(a[j] - __bfloat162float(h));
    }
}

__device__ __forceinline__ void transpose_body(
    const float* __restrict__ src, __nv_bfloat16* __restrict__ hi,
    __nv_bfloat16* __restrict__ lo, int K, int N)
{
    __shared__ float tile[32][33];
    int bn = blockIdx.x * 32, bk = blockIdx.y * 32;
    int tx = threadIdx.x, ty = threadIdx.y;
    #pragma unroll
    for (int i = 0; i < 32; i += 8)
        tile[ty + i][tx] = src[(size_t)(bk + ty + i) * N + bn + tx];
    __syncthreads();
    #pragma unroll
    for (int i = 0; i < 32; i += 8) {
        float v = tile[tx][ty + i];
        __nv_bfloat16 h = __float2bfloat16_rn(v);
        size_t o = (size_t)(bn + ty + i) * K + bk + tx;
        hi[o] = h;
        lo[o] = __float2bfloat16_rn(v - __bfloat162float(h));
    }
}

__global__ void transpose_qkvo(const float* Wq, const float* Wk, const float* Wv, const float* Wo)
{
    int z = blockIdx.z;
    const float* src = (z == 0) ? Wq : (z == 1) ? Wk : (z == 2) ? Wv : Wo;
    transpose_body(src, g_w4t_h + (size_t)z * kD * kD, g_w4t_l + (size_t)z * kD * kD, kD, kD);
}

__global__ void transpose_w1(const float* W1e)
{
    int e = blockIdx.z;
    size_t off = (size_t)e * kD * kFF;
    transpose_body(W1e + off, g_w1t_h + off, g_w1t_l + off, kD, kFF);
}

__global__ void transpose_w2(const float* W2e)
{
    int e = blockIdx.z;
    size_t off = (size_t)e * kFF * kD;
    transpose_body(W2e + off, g_w2t_h + off, g_w2t_l + off, kFF, kD);
}

// ---------------- add + layernorm ----------------
__device__ __forceinline__ float block_sum_256(float v, float* red)
{
    int tid = threadIdx.x;
    #pragma unroll
    for (int o = 16; o; o >>= 1) v += __shfl_xor_sync(0xffffffffu, v, o);
    if ((tid & 31) == 0) red[tid >> 5] = v;
    __syncthreads();
    if (tid < 8) {
        float x = red[tid];
        #pragma unroll
        for (int o = 4; o; o >>= 1) x += __shfl_xor_sync(0xffu, x, o);
        if (tid == 0) red[0] = x;
    }
    __syncthreads();
    float r = red[0];
    __syncthreads();
    return r;
}

__device__ __forceinline__ void add_ln_body(
    const float* __restrict__ A, const float* __restrict__ Bb,
    const float* __restrict__ gw, const float* __restrict__ bw,
    float* __restrict__ out, __nv_bfloat16* __restrict__ oh,
    __nv_bfloat16* __restrict__ ol)
{
    __shared__ float red[8];
    int t = blockIdx.x, tid = threadIdx.x;
    float4 av = ((const float4*)(A  + (size_t)t * kD))[tid];
    float4 bv = ((const float4*)(Bb + (size_t)t * kD))[tid];
    float vx = av.x + bv.x, vy = av.y + bv.y, vz = av.z + bv.z, vw = av.w + bv.w;
    float ssum = block_sum_256(vx + vy + vz + vw, red);
    float mu = ssum * (1.0f / kD);
    float dx = vx - mu, dy = vy - mu, dz = vz - mu, dw = vw - mu;
    float sq = block_sum_256(dx*dx + dy*dy + dz*dz + dw*dw, red);
    float rstd = rsqrtf(sq * (1.0f / kD) + kEPS);
    float4 gv = ((const float4*)gw)[tid];
    float4 be = ((const float4*)bw)[tid];
    float ovv[4] = {dx*rstd*gv.x + be.x, dy*rstd*gv.y + be.y,
                    dz*rstd*gv.z + be.z, dw*rstd*gv.w + be.w};
    ((float4*)(out + (size_t)t * kD))[tid] = make_float4(ovv[0], ovv[1], ovv[2], ovv[3]);
    if (oh) {
        size_t o = (size_t)t * kD + tid * 4;
        #pragma unroll
        for (int j = 0; j < 4; j++) {
            __nv_bfloat16 h = __float2bfloat16_rn(ovv[j]);
            oh[o + j] = h;
            ol[o + j] = __float2bfloat16_rn(ovv[j] - __bfloat162float(h));
        }
    }
}

__global__ void ln1_kernel(const float* __restrict__ x,
                           const float* __restrict__ g, const float* __restrict__ b)
{
    add_ln_body(x, g_proj, g, b, g_x1, g_x1b_h, g_x1b_l);
}

__global__ void ln2_kernel(const float* __restrict__ g, const float* __restrict__ b,
                           float* __restrict__ out)
{
    add_ln_body(g_x1, g_y, g, b, out, nullptr, nullptr);
}

// ---------------- MoE gate (top-1 argmax) ----------------
__global__ void zero_cnt()
{
    if (threadIdx.x < kE) g_cnt[threadIdx.x] = 0;
}

__global__ void gate_kernel(const float* __restrict__ Wg, const float* __restrict__ bg)
{
    int t = blockIdx.x, tid = threadIdx.x;
    float a0 = 0.f, a1 = 0.f, a2 = 0.f, a3 = 0.f;
    const float* xr = g_x1 + (size_t)t * kD;
    for (int d = tid; d < kD; d += 128) {
        float xv = xr[d];
        float4 w = ((const float4*)Wg)[d];
        a0 = fmaf(xv, w.x, a0);
        a1 = fmaf(xv, w.y, a1);
        a2 = fmaf(xv, w.z, a2);
        a3 = fmaf(xv, w.w, a3);
    }
    __shared__ float rsm[4][128];
    rsm[0][tid] = a0; rsm[1][tid] = a1; rsm[2][tid] = a2; rsm[3][tid] = a3;
    __syncthreads();
    for (int s = 64; s > 0; s >>= 1) {
        if (tid < s) {
            #pragma unroll
            for (int e = 0; e < 4; e++) rsm[e][tid] += rsm[e][tid + s];
        }
        __syncthreads();
    }
    if (tid == 0) {
        float sc[4];
        #pragma unroll
        for (int e = 0; e < 4; e++) sc[e] = rsm[e][0] + bg[e];
        int best = 0; float bvv = sc[0];
        #pragma unroll
        for (int e = 1; e < 4; e++) {
            if (sc[e] > bvv) { bvv = sc[e]; best = e; }
        }
        int pos = atomicAdd(&g_cnt[best], 1);
        g_list[best * kNT + pos] = t;
    }
}

// ---------------- launch ----------------
extern "C" void kernel_launch(void* const* d_in, const int* in_sizes, int n_in,
                              void* d_out, int out_size)
{
    const float* x    = (const float*)d_in[0];
    const float* Wq   = (const float*)d_in[2];
    const float* bq   = (const float*)d_in[3];
    const float* Wk   = (const float*)d_in[4];
    const float* bk   = (const float*)d_in[5];
    const float* Wv   = (const float*)d_in[6];
    const float* bv   = (const float*)d_in[7];
    const float* Wo   = (const float*)d_in[8];
    const float* bo   = (const float*)d_in[9];
    const float* ln1g = (const float*)d_in[10];
    const float* ln1b = (const float*)d_in[11];
    const float* Wg   = (const float*)d_in[12];
    const float* bg   = (const float*)d_in[13];
    const float* W1e  = (const float*)d_in[14];
    const float* b1e  = (const float*)d_in[15];
    const float* W2e  = (const float*)d_in[16];
    const float* b2e  = (const float*)d_in[17];
    const float* ln2g = (const float*)d_in[18];
    const float* ln2b = (const float*)d_in[19];
    float* out = (float*)d_out;

    cudaFuncSetAttribute(attn_tc, cudaFuncAttributeMaxDynamicSharedMemorySize, ATTN_SMEM);
    cudaFuncSetAttribute(qkv_tc,  cudaFuncAttributeMaxDynamicSharedMemorySize, GEMM_SMEM);
    cudaFuncSetAttribute(proj_tc, cudaFuncAttributeMaxDynamicSharedMemorySize, GEMM_SMEM);
    cudaFuncSetAttribute(moe1_tc, cudaFuncAttributeMaxDynamicSharedMemorySize, GEMM_SMEM);
    cudaFuncSetAttribute(moe2_tc, cudaFuncAttributeMaxDynamicSharedMemorySize, GEMM_SMEM);

    // side stream for prep work that can overlap the main chain
    cudaStream_t side;
    cudaEvent_t evFork, evJoin1, evJoin2;
    cudaStreamCreateWithFlags(&side, cudaStreamNonBlocking);
    cudaEventCreateWithFlags(&evFork, cudaEventDisableTiming);
    cudaEventCreateWithFlags(&evJoin1, cudaEventDisableTiming);
    cudaEventCreateWithFlags(&evJoin2, cudaEventDisableTiming);

    cudaEventRecord(evFork, 0);
    cudaStreamWaitEvent(side, evFork, 0);
    convert_x<<<kNT * kD / 4 / 256, 256, 0, side>>>(x);
    cudaEventRecord(evJoin1, side);
    transpose_w1<<<dim3(kFF/32, kD/32, kE), dim3(32, 8), 0, side>>>(W1e);
    transpose_w2<<<dim3(kD/32, kFF/32, kE), dim3(32, 8), 0, side>>>(W2e);
    cudaEventRecord(evJoin2, side);

    // main chain: attention path
    transpose_qkvo<<<dim3(kD/32, kD/32, 4), dim3(32, 8)>>>(Wq, Wk, Wv, Wo);
    cudaStreamWaitEvent(0, evJoin1, 0);
    qkv_tc<<<dim3(kD/128, kNT/128, 3), 256, GEMM_SMEM>>>(bq, bk, bv);
    attn_tc<<<dim3(kT/128, kB*kH), 256, ATTN_SMEM>>>();
    proj_tc<<<dim3(kD/128, kNT/128), 256, GEMM_SMEM>>>(bo);
    ln1_kernel<<<kNT, 256>>>(x, ln1g, ln1b);

    // MoE path
    zero_cnt<<<1, 32>>>();
    gate_kernel<<<kNT, 128>>>(Wg, bg);
    cudaStreamWaitEvent(0, evJoin2, 0);
    moe1_tc<<<dim3(kFF/128, kNT/128, kE), 256, GEMM_SMEM>>>(b1e);
    moe2_tc<<<dim3(kD/128, kNT/128, kE), 256, GEMM_SMEM>>>(b2e);
    ln2_kernel<<<kNT, 256>>>(ln2g, ln2b, out);
}

// round 9
// speedup vs baseline: 1.1610x; 1.1219x over previous
#include <cuda_runtime.h>
#include <cuda_bf16.h>
#include <math.h>
#include <stdint.h>

// ---------------- problem constants ----------------
constexpr int kB  = 2;
constexpr int kT  = 2048;
constexpr int kD  = 1024;
constexpr int kH  = 16;
constexpr int kDH = 64;
constexpr int kFF = 4096;
constexpr int kE  = 4;
constexpr int kNT = kB * kT;           // 4096 tokens
constexpr float kEPS = 1e-5f;

// ---------------- scratch (device globals: allocation-free) ----------------
__device__ float g_proj[kNT * kD];
__device__ float g_x1[kNT * kD];
__device__ float g_y[kNT * kD];
__device__ int   g_cnt[kE];
__device__ int   g_list[kE * kNT];

// bf16 hi/lo planes (activations)
__device__ __nv_bfloat16 g_xb_h[kNT * kD],  g_xb_l[kNT * kD];
__device__ __nv_bfloat16 g_qb_h[kNT * kD],  g_qb_l[kNT * kD];
__device__ __nv_bfloat16 g_kb_h[kNT * kD],  g_kb_l[kNT * kD];
__device__ __nv_bfloat16 g_vb_h[kNT * kD],  g_vb_l[kNT * kD];
__device__ __nv_bfloat16 g_ab_h[kNT * kD],  g_ab_l[kNT * kD];     // attn out
__device__ __nv_bfloat16 g_x1b_h[kNT * kD], g_x1b_l[kNT * kD];
__device__ __nv_bfloat16 g_hb_h[(size_t)kNT * kFF], g_hb_l[(size_t)kNT * kFF];

// bf16 hi/lo planes (transposed weights, [N][K] K-major)
__device__ __nv_bfloat16 g_w4t_h[4 * kD * kD], g_w4t_l[4 * kD * kD];   // Wq,Wk,Wv,Wo
__device__ __nv_bfloat16 g_w1t_h[(size_t)kE * kFF * kD], g_w1t_l[(size_t)kE * kFF * kD];
__device__ __nv_bfloat16 g_w2t_h[(size_t)kE * kFF * kD], g_w2t_l[(size_t)kE * kFF * kD];

// ==================== PTX helpers (base sm_103 features only) ====================
__device__ __forceinline__ uint32_t smem_u32(const void* p) {
    uint32_t a;
    asm("{ .reg .u64 t; cvta.to.shared.u64 t, %1; cvt.u32.u64 %0, t; }" : "=r"(a) : "l"(p));
    return a;
}

__device__ __forceinline__ void cp_async16(uint32_t s, const void* g, int sz) {
    asm volatile("cp.async.cg.shared.global [%0], [%1], 16, %2;"
                 :: "r"(s), "l"(g), "r"(sz) : "memory");
}
#define CP_COMMIT()  asm volatile("cp.async.commit_group;" ::: "memory")
#define CP_WAIT(n)   asm volatile("cp.async.wait_group %0;" :: "n"(n) : "memory")

__device__ __forceinline__ void ldsm_x4(uint32_t& r0, uint32_t& r1, uint32_t& r2,
                                        uint32_t& r3, uint32_t addr) {
    asm volatile("ldmatrix.sync.aligned.m8n8.x4.shared.b16 {%0,%1,%2,%3}, [%4];"
                 : "=r"(r0), "=r"(r1), "=r"(r2), "=r"(r3) : "r"(addr));
}
__device__ __forceinline__ void ldsm_x4_t(uint32_t& r0, uint32_t& r1, uint32_t& r2,
                                          uint32_t& r3, uint32_t addr) {
    asm volatile("ldmatrix.sync.aligned.m8n8.x4.trans.shared.b16 {%0,%1,%2,%3}, [%4];"
                 : "=r"(r0), "=r"(r1), "=r"(r2), "=r"(r3) : "r"(addr));
}

__device__ __forceinline__ void mma16816(float* d, const uint32_t* a,
                                         uint32_t b0, uint32_t b1) {
    asm volatile("mma.sync.aligned.m16n8k16.row.col.f32.bf16.bf16.f32 "
                 "{%0,%1,%2,%3}, {%4,%5,%6,%7}, {%8,%9}, {%0,%1,%2,%3};"
                 : "+f"(d[0]), "+f"(d[1]), "+f"(d[2]), "+f"(d[3])
                 : "r"(a[0]), "r"(a[1]), "r"(a[2]), "r"(a[3]), "r"(b0), "r"(b1));
}

// split (f0,f1) into packed bf16 hi and lo planes
__device__ __forceinline__ void split2(float f0, float f1, uint32_t& h, uint32_t& l) {
    __nv_bfloat162 hv = __floats2bfloat162_rn(f0, f1);
    float r0 = f0 - __bfloat162float(hv.x);
    float r1 = f1 - __bfloat162float(hv.y);
    __nv_bfloat162 lv = __floats2bfloat162_rn(r0, r1);
    h = *reinterpret_cast<uint32_t*>(&hv);
    l = *reinterpret_cast<uint32_t*>(&lv);
}

// ==================== mma.sync split-bf16 GEMM ====================
// Block 128x128, 256 threads (8 warps, 4Mx2N), warp tile 32x64, K-chunk 32.
// XOR-swizzled 64B rows (no padding): 3-stage cp.async pipeline.
constexpr int kPlaneB = 128 * 64;              // 8192 B per plane (128 rows x 64B)
constexpr int kStageB = 4 * kPlaneB;           // Ah Al Bh Bl = 32768
constexpr int GEMM_SMEM = 3 * kStageB;         // 98304 (2 CTAs/SM = 192KB)

// swizzled byte offset of (row, chunkByte) within an 8KB plane; chunkByte in {0,16,32,48}
__device__ __forceinline__ uint32_t swz(int row, int cb) {
    return (uint32_t)(row * 64 + ((((cb >> 4) ^ ((row >> 1) & 3))) << 4));
}

struct GemmPtrs {
    const __nv_bfloat16 *aH0, *aL0, *aH1, *aL1;
    const __nv_bfloat16 *bH0, *bL0, *bH1, *bL1;
    int v0, v1, c8;
};

__device__ __forceinline__ void fill_stage(uint32_t sb, int k0, const GemmPtrs& P)
{
    int row = threadIdx.x >> 2;                 // 0..63
    int cb  = (threadIdx.x & 3) * 16;
    uint32_t o0 = swz(row, cb);
    uint32_t o1 = o0 + 64 * 64;                 // row+64 keeps same swizzle phase
    int g = k0 + P.c8;
    cp_async16(sb + o0,               P.aH0 + g, P.v0 ? 16 : 0);
    cp_async16(sb + o1,               P.aH1 + g, P.v1 ? 16 : 0);
    cp_async16(sb + kPlaneB + o0,     P.aL0 + g, P.v0 ? 16 : 0);
    cp_async16(sb + kPlaneB + o1,     P.aL1 + g, P.v1 ? 16 : 0);
    cp_async16(sb + 2*kPlaneB + o0,   P.bH0 + g, 16);
    cp_async16(sb + 2*kPlaneB + o1,   P.bH1 + g, 16);
    cp_async16(sb + 3*kPlaneB + o0,   P.bL0 + g, 16);
    cp_async16(sb + 3*kPlaneB + o1,   P.bL1 + g, 16);
}

// mode 0: C = acc + bias (fp32)
// mode 1: relu(acc+bias) -> Chi/Clo bf16 planes
// mode 2: (acc+bias)*scale -> Chi/Clo bf16 planes
__device__ __forceinline__ void gemm_tc(
    const __nv_bfloat16* __restrict__ Ah, const __nv_bfloat16* __restrict__ Al,
    const __nv_bfloat16* __restrict__ Bh, const __nv_bfloat16* __restrict__ Bl,
    const float* __restrict__ bias, int K, int count, const int* __restrict__ list,
    int mode, float* __restrict__ C,
    __nv_bfloat16* __restrict__ Chi, __nv_bfloat16* __restrict__ Clo, int ldc,
    float scale)
{
    extern __shared__ char sm[];
    const int tid  = threadIdx.x;
    const int wid  = tid >> 5, lane = tid & 31;
    const int rowBase = blockIdx.y * 128;
    const int colBase = blockIdx.x * 128;
    if (rowBase >= count) return;

    GemmPtrs P;
    {
        int r0 = tid >> 2;
        int gr0 = rowBase + r0, gr1 = rowBase + r0 + 64;
        P.v0 = gr0 < count;
        P.v1 = gr1 < count;
        int rr0 = P.v0 ? (list ? list[gr0] : gr0) : 0;
        int rr1 = P.v1 ? (list ? list[gr1] : gr1) : 0;
        P.aH0 = Ah + (size_t)rr0 * K;  P.aL0 = Al + (size_t)rr0 * K;
        P.aH1 = Ah + (size_t)rr1 * K;  P.aL1 = Al + (size_t)rr1 * K;
        P.bH0 = Bh + (size_t)(colBase + r0) * K;
        P.bH1 = Bh + (size_t)(colBase + r0 + 64) * K;
        P.bL0 = Bl + (size_t)(colBase + r0) * K;
        P.bL1 = Bl + (size_t)(colBase + r0 + 64) * K;
        P.c8  = (tid & 3) * 8;
    }
    const uint32_t smb = smem_u32(sm);

    const int wM = (wid & 3) * 32;
    const int wN = (wid >> 2) * 64;

    float acc[2][8][4];
    #pragma unroll
    for (int i = 0; i < 2; i++)
        #pragma unroll
        for (int j = 0; j < 8; j++)
            #pragma unroll
            for (int d = 0; d < 4; d++) acc[i][j][d] = 0.f;

    // precomputed swizzled ldsm offsets (loop-invariant)
    const int aCol = (lane >> 4) * 16;
    const int bRow = (lane & 7) + ((lane >> 4) & 1) * 8;
    const int bCol = ((lane >> 3) & 1) * 16;
    uint32_t offA[2][2], offB[4][2];
    #pragma unroll
    for (int mi = 0; mi < 2; mi++)
        #pragma unroll
        for (int s = 0; s < 2; s++)
            offA[mi][s] = swz(wM + mi * 16 + (lane & 15), s * 32 + aCol);
    #pragma unroll
    for (int nj = 0; nj < 4; nj++)
        #pragma unroll
        for (int s = 0; s < 2; s++)
            offB[nj][s] = 2 * kPlaneB + swz(wN + nj * 16 + bRow, s * 32 + bCol);

    const int nc = K / 32;
    // 3-stage prologue: chunks 0 and 1 in flight
    fill_stage(smb, 0, P);
    CP_COMMIT();
    fill_stage(smb + kStageB, 32, P);
    CP_COMMIT();

    int buf = 0;
    for (int c = 0; c < nc; c++) {
        if (c + 1 < nc) { CP_WAIT(1); } else { CP_WAIT(0); }
        __syncthreads();
        if (c + 2 < nc) {
            int nb = buf + 2; if (nb >= 3) nb -= 3;
            fill_stage(smb + nb * kStageB, (c + 2) * 32, P);
            CP_COMMIT();
        }

        uint32_t st = smb + buf * kStageB;
        #pragma unroll
        for (int s = 0; s < 2; s++) {
            uint32_t ah[2][4], al[2][4];
            #pragma unroll
            for (int mi = 0; mi < 2; mi++) {
                uint32_t ra = st + offA[mi][s];
                ldsm_x4(ah[mi][0], ah[mi][1], ah[mi][2], ah[mi][3], ra);
                ldsm_x4(al[mi][0], al[mi][1], al[mi][2], al[mi][3], ra + kPlaneB);
            }
            #pragma unroll
            for (int njp = 0; njp < 4; njp++) {
                uint32_t rb = st + offB[njp][s];
                uint32_t bh[4], bl[4];
                ldsm_x4(bh[0], bh[1], bh[2], bh[3], rb);
                ldsm_x4(bl[0], bl[1], bl[2], bl[3], rb + kPlaneB);
                #pragma unroll
                for (int mi = 0; mi < 2; mi++) {
                    #pragma unroll
                    for (int half = 0; half < 2; half++) {
                        float* d = acc[mi][njp * 2 + half];
                        mma16816(d, ah[mi], bh[half * 2], bh[half * 2 + 1]);
                        mma16816(d, ah[mi], bl[half * 2], bl[half * 2 + 1]);
                        mma16816(d, al[mi], bh[half * 2], bh[half * 2 + 1]);
                    }
                }
            }
        }
        buf = (buf < 2) ? buf + 1 : 0;
    }

    #pragma unroll
    for (int mi = 0; mi < 2; mi++) {
        #pragma unroll
        for (int dd = 0; dd < 2; dd++) {
            int lrow = rowBase + wM + mi * 16 + (lane >> 2) + dd * 8;
            if (lrow >= count) continue;
            int orow = list ? list[lrow] : lrow;
            #pragma unroll
            for (int nj = 0; nj < 8; nj++) {
                int n = colBase + wN + nj * 8 + (lane & 3) * 2;
                float v0 = acc[mi][nj][dd * 2 + 0] + bias[n];
                float v1 = acc[mi][nj][dd * 2 + 1] + bias[n + 1];
                if (mode == 0) {
                    *reinterpret_cast<float2*>(C + (size_t)orow * ldc + n)
                        = make_float2(v0, v1);
                } else {
                    if (mode == 1) { v0 = fmaxf(v0, 0.f); v1 = fmaxf(v1, 0.f); }
                    else           { v0 *= scale; v1 *= scale; }
                    size_t o = (size_t)orow * ldc + n;
                    uint32_t hh, ll;
                    split2(v0, v1, hh, ll);
                    *reinterpret_cast<uint32_t*>(Chi + o) = hh;
                    *reinterpret_cast<uint32_t*>(Clo + o) = ll;
                }
            }
        }
    }
}

// ---------------- GEMM wrappers ----------------
__global__ void __launch_bounds__(256, 2) qkv_tc(const float* bq, const float* bk, const float* bv)
{
    int z = blockIdx.z;
    const __nv_bfloat16* bh = g_w4t_h + (size_t)z * kD * kD;
    const __nv_bfloat16* bl = g_w4t_l + (size_t)z * kD * kD;
    __nv_bfloat16* ch = (z == 0) ? g_qb_h : (z == 1) ? g_kb_h : g_vb_h;
    __nv_bfloat16* cl = (z == 0) ? g_qb_l : (z == 1) ? g_kb_l : g_vb_l;
    const float* bias = (z == 0) ? bq : (z == 1) ? bk : bv;
    float scale = (z == 0) ? 0.125f : 1.0f;
    gemm_tc(g_xb_h, g_xb_l, bh, bl, bias, kD, kNT, nullptr, 2, nullptr, ch, cl, kD, scale);
}

__global__ void __launch_bounds__(256, 2) proj_tc(const float* bo)
{
    gemm_tc(g_ab_h, g_ab_l, g_w4t_h + (size_t)3 * kD * kD, g_w4t_l + (size_t)3 * kD * kD,
            bo, kD, kNT, nullptr, 0, g_proj, nullptr, nullptr, kD, 1.f);
}

__global__ void __launch_bounds__(256, 2) moe1_tc(const float* b1e)
{
    int e = blockIdx.z;
    int cnt = g_cnt[e];
    gemm_tc(g_x1b_h, g_x1b_l,
            g_w1t_h + (size_t)e * kFF * kD, g_w1t_l + (size_t)e * kFF * kD,
            b1e + (size_t)e * kFF, kD, cnt, g_list + e * kNT,
            1, nullptr, g_hb_h, g_hb_l, kFF, 1.f);
}

__global__ void __launch_bounds__(256, 2) moe2_tc(const float* b2e)
{
    int e = blockIdx.z;
    int cnt = g_cnt[e];
    gemm_tc(g_hb_h, g_hb_l,
            g_w2t_h + (size_t)e * kFF * kD, g_w2t_l + (size_t)e * kFF * kD,
            b2e + (size_t)e * kD, kFF, cnt, g_list + e * kNT,
            0, g_y, nullptr, nullptr, kD, 1.f);
}

// ==================== HMMA flash attention (causal, split bf16) ====================
// Q pre-scaled by 0.125 in qkv epilogue. q-tile 128 (8 warps x m16), kv-tile 64.
constexpr int kARS    = 144;                   // padded row bytes (64 bf16 + 8 pad)
constexpr int kAPlane = 64 * kARS;             // 9216
constexpr int kAStage = 4 * kAPlane;           // Kh Kl Vh Vl = 36864
constexpr int ATTN_SMEM = 2 * kAStage;         // 73728

__device__ __forceinline__ void fill_kv(uint32_t dst, int b, int h, int kbase)
{
    const __nv_bfloat16* srcs[4] = {g_kb_h, g_kb_l, g_vb_h, g_vb_l};
    #pragma unroll
    for (int i = 0; i < 8; i++) {
        int lin = threadIdx.x + 256 * i;
        int ch = lin & 7, row = (lin >> 3) & 63, pl = lin >> 9;
        const __nv_bfloat16* src = srcs[pl]
            + ((size_t)(b * kT + kbase + row) * kD + h * 64 + ch * 8);
        cp_async16(dst + pl * kAPlane + row * kARS + ch * 16, src, 16);
    }
}

__global__ void __launch_bounds__(256) attn_tc()
{
    extern __shared__ char sa[];
    const uint32_t smb = smem_u32(sa);
    const int tid = threadIdx.x, wid = tid >> 5, lane = tid & 31;
    const int qt = gridDim.x - 1 - blockIdx.x;   // longest-first launch order
    const int bh = blockIdx.y;
    const int b = bh >> 4, h = bh & 15;
    const int qb = qt * 128;
    const int wr0 = qb + wid * 16;               // warp's first q row

    // ---- load Q tile (128 x 64, hi/lo) into stage1 region ----
    #pragma unroll
    for (int i = 0; i < 8; i++) {
        int lin = tid + 256 * i;
        int ch = lin & 7, row = (lin >> 3) & 127, pl = lin >> 10;
        const __nv_bfloat16* src = (pl ? g_qb_l : g_qb_h)
            + ((size_t)(b * kT + qb + row) * kD + h * 64 + ch * 8);
        cp_async16(smb + kAStage + pl * (128 * kARS) + row * kARS + ch * 16, src, 16);
    }
    CP_COMMIT();
    fill_kv(smb, b, h, 0);
    CP_COMMIT();
    CP_WAIT(0);
    __syncthreads();

    // ---- Q fragments to registers ----
    uint32_t qh[4][4], ql[4][4];
    #pragma unroll
    for (int ks = 0; ks < 4; ks++) {
        uint32_t addr = smb + kAStage + (wid * 16 + (lane & 15)) * kARS
                      + ks * 32 + (lane >> 4) * 16;
        ldsm_x4(qh[ks][0], qh[ks][1], qh[ks][2], qh[ks][3], addr);
        ldsm_x4(ql[ks][0], ql[ks][1], ql[ks][2], ql[ks][3], addr + 128 * kARS);
    }

    float m0 = -1e30f, m1 = -1e30f, l0 = 0.f, l1 = 0.f;
    float o[8][4];
    #pragma unroll
    for (int g = 0; g < 8; g++)
        #pragma unroll
        for (int d = 0; d < 4; d++) o[g][d] = 0.f;

    const int ktmax = 2 * qt + 2;
    for (int kt = 0; kt < ktmax; kt++) {
        CP_WAIT(0);
        __syncthreads();
        if (kt + 1 < ktmax) {
            fill_kv(smb + ((kt + 1) & 1) * kAStage, b, h, (kt + 1) * 64);
            CP_COMMIT();
        }

        const int kbase = kt * 64;
        if (kbase <= wr0 + 15) {
            const uint32_t st = smb + (kt & 1) * kAStage;

            // ---- S = Q K^T (3-pass) ----
            float s[8][4];
            #pragma unroll
            for (int j = 0; j < 8; j++)
                #pragma unroll
                for (int d = 0; d < 4; d++) s[j][d] = 0.f;

            #pragma unroll
            for (int ks = 0; ks < 4; ks++) {
                #pragma unroll
                for (int ng = 0; ng < 4; ng++) {
                    uint32_t a = st + (ng * 16 + (lane & 7) + (lane >> 4) * 8) * kARS
                               + ks * 32 + ((lane >> 3) & 1) * 16;
                    uint32_t k0, k1, k2, k3, e0, e1, e2, e3;
                    ldsm_x4(k0, k1, k2, k3, a);
                    ldsm_x4(e0, e1, e2, e3, a + kAPlane);
                    mma16816(s[2*ng],   qh[ks], k0, k1);
                    mma16816(s[2*ng],   qh[ks], e0, e1);
                    mma16816(s[2*ng],   ql[ks], k0, k1);
                    mma16816(s[2*ng+1], qh[ks], k2, k3);
                    mma16816(s[2*ng+1], qh[ks], e2, e3);
                    mma16816(s[2*ng+1], ql[ks], k2, k3);
                }
            }

            // ---- mask (straddling tiles only) ----
            const int r0 = wr0 + (lane >> 2), r1 = r0 + 8;
            if (kbase + 63 > wr0) {
                #pragma unroll
                for (int j = 0; j < 8; j++) {
                    int c = kbase + j * 8 + (lane & 3) * 2;
                    if (c > r0)     s[j][0] = -1e30f;
                    if (c + 1 > r0) s[j][1] = -1e30f;
                    if (c > r1)     s[j][2] = -1e30f;
                    if (c + 1 > r1) s[j][3] = -1e30f;
                }
            }

            // ---- online softmax ----
            float rm0 = -1e30f, rm1 = -1e30f;
            #pragma unroll
            for (int j = 0; j < 8; j++) {
                rm0 = fmaxf(rm0, fmaxf(s[j][0], s[j][1]));
                rm1 = fmaxf(rm1, fmaxf(s[j][2], s[j][3]));
            }
            rm0 = fmaxf(rm0, __shfl_xor_sync(0xffffffffu, rm0, 1));
            rm0 = fmaxf(rm0, __shfl_xor_sync(0xffffffffu, rm0, 2));
            rm1 = fmaxf(rm1, __shfl_xor_sync(0xffffffffu, rm1, 1));
            rm1 = fmaxf(rm1, __shfl_xor_sync(0xffffffffu, rm1, 2));
            float mn0 = fmaxf(m0, rm0), mn1 = fmaxf(m1, rm1);
            float cr0 = __expf(m0 - mn0), cr1 = __expf(m1 - mn1);
            m0 = mn0; m1 = mn1;
            float ps0 = 0.f, ps1 = 0.f;
            #pragma unroll
            for (int j = 0; j < 8; j++) {
                s[j][0] = __expf(s[j][0] - m0);
                s[j][1] = __expf(s[j][1] - m0);
                s[j][2] = __expf(s[j][2] - m1);
                s[j][3] = __expf(s[j][3] - m1);
                ps0 += s[j][0] + s[j][1];
                ps1 += s[j][2] + s[j][3];
            }
            ps0 += __shfl_xor_sync(0xffffffffu, ps0, 1);
            ps0 += __shfl_xor_sync(0xffffffffu, ps0, 2);
            ps1 += __shfl_xor_sync(0xffffffffu, ps1, 1);
            ps1 += __shfl_xor_sync(0xffffffffu, ps1, 2);
            l0 = l0 * cr0 + ps0;
            l1 = l1 * cr1 + ps1;
            #pragma unroll
            for (int g = 0; g < 8; g++) {
                o[g][0] *= cr0; o[g][1] *= cr0;
                o[g][2] *= cr1; o[g][3] *= cr1;
            }

            // ---- O += P V (3-pass, P repacked in registers) ----
            #pragma unroll
            for (int t = 0; t < 4; t++) {
                uint32_t ph[4], pl[4];
                split2(s[2*t][0],   s[2*t][1],   ph[0], pl[0]);
                split2(s[2*t][2],   s[2*t][3],   ph[1], pl[1]);
                split2(s[2*t+1][0], s[2*t+1][1], ph[2], pl[2]);
                split2(s[2*t+1][2], s[2*t+1][3], ph[3], pl[3]);
                #pragma unroll
                for (int dg = 0; dg < 4; dg++) {
                    uint32_t a = st + 2 * kAPlane
                               + (t * 16 + (lane & 7) + ((lane >> 3) & 1) * 8) * kARS
                               + dg * 32 + (lane >> 4) * 16;
                    uint32_t v0, v1, v2, v3, w0, w1, w2, w3;
                    ldsm_x4_t(v0, v1, v2, v3, a);
                    ldsm_x4_t(w0, w1, w2, w3, a + kAPlane);
                    mma16816(o[2*dg],   ph, v0, v1);
                    mma16816(o[2*dg],   ph, w0, w1);
                    mma16816(o[2*dg],   pl, v0, v1);
                    mma16816(o[2*dg+1], ph, v2, v3);
                    mma16816(o[2*dg+1], ph, w2, w3);
                    mma16816(o[2*dg+1], pl, v2, v3);
                }
            }
        }
    }

    // ---- epilogue: O/l -> bf16 hi/lo planes ----
    const float inv0 = 1.f / l0, inv1 = 1.f / l1;
    const size_t tok0 = (size_t)(b * kT) + wr0 + (lane >> 2);
    #pragma unroll
    for (int g = 0; g < 8; g++) {
        int col = h * 64 + g * 8 + (lane & 3) * 2;
        uint32_t hh, ll;
        split2(o[g][0] * inv0, o[g][1] * inv0, hh, ll);
        *reinterpret_cast<uint32_t*>(g_ab_h + tok0 * kD + col) = hh;
        *reinterpret_cast<uint32_t*>(g_ab_l + tok0 * kD + col) = ll;
        split2(o[g][2] * inv1, o[g][3] * inv1, hh, ll);
        *reinterpret_cast<uint32_t*>(g_ab_h + (tok0 + 8) * kD + col) = hh;
        *reinterpret_cast<uint32_t*>(g_ab_l + (tok0 + 8) * kD + col) = ll;
    }
}

// ---------------- conversion kernels ----------------
__global__ void convert_x(const float* __restrict__ x)
{
    int i = blockIdx.x * 256 + threadIdx.x;
    float4 v = ((const float4*)x)[i];
    size_t o = (size_t)i * 4;
    float a[4] = {v.x, v.y, v.z, v.w};
    #pragma unroll
    for (int j = 0; j < 4; j++) {
        __nv_bfloat16 h = __float2bfloat16_rn(a[j]);
        g_xb_h[o + j] = h;
        g_xb_l[o + j] = __float2bfloat16_rn(a[j] - __bfloat162float(h));
    }
}

__device__ __forceinline__ void transpose_body(
    const float* __restrict__ src, __nv_bfloat16* __restrict__ hi,
    __nv_bfloat16* __restrict__ lo, int K, int N)
{
    __shared__ float tile[32][33];
    int bn = blockIdx.x * 32, bk = blockIdx.y * 32;
    int tx = threadIdx.x, ty = threadIdx.y;
    #pragma unroll
    for (int i = 0; i < 32; i += 8)
        tile[ty + i][tx] = src[(size_t)(bk + ty + i) * N + bn + tx];
    __syncthreads();
    #pragma unroll
    for (int i = 0; i < 32; i += 8) {
        float v = tile[tx][ty + i];
        __nv_bfloat16 h = __float2bfloat16_rn(v);
        size_t o = (size_t)(bn + ty + i) * K + bk + tx;
        hi[o] = h;
        lo[o] = __float2bfloat16_rn(v - __bfloat162float(h));
    }
}

__global__ void transpose_qkvo(const float* Wq, const float* Wk, const float* Wv, const float* Wo)
{
    int z = blockIdx.z;
    const float* src = (z == 0) ? Wq : (z == 1) ? Wk : (z == 2) ? Wv : Wo;
    transpose_body(src, g_w4t_h + (size_t)z * kD * kD, g_w4t_l + (size_t)z * kD * kD, kD, kD);
}

__global__ void transpose_w1(const float* W1e)
{
    int e = blockIdx.z;
    size_t off = (size_t)e * kD * kFF;
    transpose_body(W1e + off, g_w1t_h + off, g_w1t_l + off, kD, kFF);
}

__global__ void transpose_w2(const float* W2e)
{
    int e = blockIdx.z;
    size_t off = (size_t)e * kFF * kD;
    transpose_body(W2e + off, g_w2t_h + off, g_w2t_l + off, kFF, kD);
}

// ---------------- add + layernorm ----------------
__device__ __forceinline__ float block_sum_256(float v, float* red)
{
    int tid = threadIdx.x;
    #pragma unroll
    for (int o = 16; o; o >>= 1) v += __shfl_xor_sync(0xffffffffu, v, o);
    if ((tid & 31) == 0) red[tid >> 5] = v;
    __syncthreads();
    if (tid < 8) {
        float x = red[tid];
        #pragma unroll
        for (int o = 4; o; o >>= 1) x += __shfl_xor_sync(0xffu, x, o);
        if (tid == 0) red[0] = x;
    }
    __syncthreads();
    float r = red[0];
    __syncthreads();
    return r;
}

__device__ __forceinline__ void add_ln_body(
    const float* __restrict__ A, const float* __restrict__ Bb,
    const float* __restrict__ gw, const float* __restrict__ bw,
    float* __restrict__ out, __nv_bfloat16* __restrict__ oh,
    __nv_bfloat16* __restrict__ ol)
{
    __shared__ float red[8];
    int t = blockIdx.x, tid = threadIdx.x;
    float4 av = ((const float4*)(A  + (size_t)t * kD))[tid];
    float4 bv = ((const float4*)(Bb + (size_t)t * kD))[tid];
    float vx = av.x + bv.x, vy = av.y + bv.y, vz = av.z + bv.z, vw = av.w + bv.w;
    float ssum = block_sum_256(vx + vy + vz + vw, red);
    float mu = ssum * (1.0f / kD);
    float dx = vx - mu, dy = vy - mu, dz = vz - mu, dw = vw - mu;
    float sq = block_sum_256(dx*dx + dy*dy + dz*dz + dw*dw, red);
    float rstd = rsqrtf(sq * (1.0f / kD) + kEPS);
    float4 gv = ((const float4*)gw)[tid];
    float4 be = ((const float4*)bw)[tid];
    float ovv[4] = {dx*rstd*gv.x + be.x, dy*rstd*gv.y + be.y,
                    dz*rstd*gv.z + be.z, dw*rstd*gv.w + be.w};
    ((float4*)(out + (size_t)t * kD))[tid] = make_float4(ovv[0], ovv[1], ovv[2], ovv[3]);
    if (oh) {
        size_t o = (size_t)t * kD + tid * 4;
        #pragma unroll
        for (int j = 0; j < 4; j++) {
            __nv_bfloat16 h = __float2bfloat16_rn(ovv[j]);
            oh[o + j] = h;
            ol[o + j] = __float2bfloat16_rn(ovv[j] - __bfloat162float(h));
        }
    }
}

__global__ void ln1_kernel(const float* __restrict__ x,
                           const float* __restrict__ g, const float* __restrict__ b)
{
    add_ln_body(x, g_proj, g, b, g_x1, g_x1b_h, g_x1b_l);
}

__global__ void ln2_kernel(const float* __restrict__ g, const float* __restrict__ b,
                           float* __restrict__ out)
{
    add_ln_body(g_x1, g_y, g, b, out, nullptr, nullptr);
}

// ---------------- MoE gate (top-1 argmax) ----------------
__global__ void zero_cnt()
{
    if (threadIdx.x < kE) g_cnt[threadIdx.x] = 0;
}

__global__ void gate_kernel(const float* __restrict__ Wg, const float* __restrict__ bg)
{
    int t = blockIdx.x, tid = threadIdx.x;
    float a0 = 0.f, a1 = 0.f, a2 = 0.f, a3 = 0.f;
    const float* xr = g_x1 + (size_t)t * kD;
    for (int d = tid; d < kD; d += 128) {
        float xv = xr[d];
        float4 w = ((const float4*)Wg)[d];
        a0 = fmaf(xv, w.x, a0);
        a1 = fmaf(xv, w.y, a1);
        a2 = fmaf(xv, w.z, a2);
        a3 = fmaf(xv, w.w, a3);
    }
    __shared__ float rsm[4][128];
    rsm[0][tid] = a0; rsm[1][tid] = a1; rsm[2][tid] = a2; rsm[3][tid] = a3;
    __syncthreads();
    for (int s = 64; s > 0; s >>= 1) {
        if (tid < s) {
            #pragma unroll
            for (int e = 0; e < 4; e++) rsm[e][tid] += rsm[e][tid + s];
        }
        __syncthreads();
    }
    if (tid == 0) {
        float sc[4];
        #pragma unroll
        for (int e = 0; e < 4; e++) sc[e] = rsm[e][0] + bg[e];
        int best = 0; float bvv = sc[0];
        #pragma unroll
        for (int e = 1; e < 4; e++) {
            if (sc[e] > bvv) { bvv = sc[e]; best = e; }
        }
        int pos = atomicAdd(&g_cnt[best], 1);
        g_list[best * kNT + pos] = t;
    }
}

// ---------------- launch ----------------
extern "C" void kernel_launch(void* const* d_in, const int* in_sizes, int n_in,
                              void* d_out, int out_size)
{
    const float* x    = (const float*)d_in[0];
    const float* Wq   = (const float*)d_in[2];
    const float* bq   = (const float*)d_in[3];
    const float* Wk   = (const float*)d_in[4];
    const float* bk   = (const float*)d_in[5];
    const float* Wv   = (const float*)d_in[6];
    const float* bv   = (const float*)d_in[7];
    const float* Wo   = (const float*)d_in[8];
    const float* bo   = (const float*)d_in[9];
    const float* ln1g = (const float*)d_in[10];
    const float* ln1b = (const float*)d_in[11];
    const float* Wg   = (const float*)d_in[12];
    const float* bg   = (const float*)d_in[13];
    const float* W1e  = (const float*)d_in[14];
    const float* b1e  = (const float*)d_in[15];
    const float* W2e  = (const float*)d_in[16];
    const float* b2e  = (const float*)d_in[17];
    const float* ln2g = (const float*)d_in[18];
    const float* ln2b = (const float*)d_in[19];
    float* out = (float*)d_out;

    cudaFuncSetAttribute(attn_tc, cudaFuncAttributeMaxDynamicSharedMemorySize, ATTN_SMEM);
    cudaFuncSetAttribute(qkv_tc,  cudaFuncAttributeMaxDynamicSharedMemorySize, GEMM_SMEM);
    cudaFuncSetAttribute(proj_tc, cudaFuncAttributeMaxDynamicSharedMemorySize, GEMM_SMEM);
    cudaFuncSetAttribute(moe1_tc, cudaFuncAttributeMaxDynamicSharedMemorySize, GEMM_SMEM);
    cudaFuncSetAttribute(moe2_tc, cudaFuncAttributeMaxDynamicSharedMemorySize, GEMM_SMEM);

    // side stream for prep work that can overlap the main chain
    cudaStream_t side;
    cudaEvent_t evFork, evJoin1, evJoin2;
    cudaStreamCreateWithFlags(&side, cudaStreamNonBlocking);
    cudaEventCreateWithFlags(&evFork, cudaEventDisableTiming);
    cudaEventCreateWithFlags(&evJoin1, cudaEventDisableTiming);
    cudaEventCreateWithFlags(&evJoin2, cudaEventDisableTiming);

    cudaEventRecord(evFork, 0);
    cudaStreamWaitEvent(side, evFork, 0);
    convert_x<<<kNT * kD / 4 / 256, 256, 0, side>>>(x);
    cudaEventRecord(evJoin1, side);
    transpose_w1<<<dim3(kFF/32, kD/32, kE), dim3(32, 8), 0, side>>>(W1e);
    transpose_w2<<<dim3(kD/32, kFF/32, kE), dim3(32, 8), 0, side>>>(W2e);
    cudaEventRecord(evJoin2, side);

    // main chain: attention path
    transpose_qkvo<<<dim3(kD/32, kD/32, 4), dim3(32, 8)>>>(Wq, Wk, Wv, Wo);
    cudaStreamWaitEvent(0, evJoin1, 0);
    qkv_tc<<<dim3(kD/128, kNT/128, 3), 256, GEMM_SMEM>>>(bq, bk, bv);
    attn_tc<<<dim3(kT/128, kB*kH), 256, ATTN_SMEM>>>();
    proj_tc<<<dim3(kD/128, kNT/128), 256, GEMM_SMEM>>>(bo);
    ln1_kernel<<<kNT, 256>>>(x, ln1g, ln1b);

    // MoE path
    zero_cnt<<<1, 32>>>();
    gate_kernel<<<kNT, 128>>>(Wg, bg);
    cudaStreamWaitEvent(0, evJoin2, 0);
    moe1_tc<<<dim3(kFF/128, kNT/128, kE), 256, GEMM_SMEM>>>(b1e);
    moe2_tc<<<dim3(kD/128, kNT/128, kE), 256, GEMM_SMEM>>>(b2e);
    ln2_kernel<<<kNT, 256>>>(ln2g, ln2b, out);
}

// round 10
// speedup vs baseline: 1.6297x; 1.4037x over previous
#include <cuda_runtime.h>
#include <cuda_fp16.h>
#include <math.h>
#include <stdint.h>

// ---------------- problem constants ----------------
constexpr int kB  = 2;
constexpr int kT  = 2048;
constexpr int kD  = 1024;
constexpr int kH  = 16;
constexpr int kDH = 64;
constexpr int kFF = 4096;
constexpr int kE  = 4;
constexpr int kNT = kB * kT;           // 4096 tokens
constexpr float kEPS = 1e-5f;

// ---------------- scratch (device globals: allocation-free) ----------------
__device__ float g_proj[kNT * kD];
__device__ float g_x1[kNT * kD];
__device__ float g_y[kNT * kD];
__device__ int   g_cnt[kE];
__device__ int   g_list[kE * kNT];

// fp16 planes: A-side arrays hi only; K/V and weights hi+lo
__device__ __half g_xb_h[kNT * kD];
__device__ __half g_qb_h[kNT * kD];
__device__ __half g_kb_h[kNT * kD],  g_kb_l[kNT * kD];
__device__ __half g_vb_h[kNT * kD],  g_vb_l[kNT * kD];
__device__ __half g_ab_h[kNT * kD];
__device__ __half g_x1b_h[kNT * kD];
__device__ __half g_hb_h[(size_t)kNT * kFF];

__device__ __half g_w4t_h[4 * kD * kD], g_w4t_l[4 * kD * kD];   // Wq,Wk,Wv,Wo [N][K]
__device__ __half g_w1t_h[(size_t)kE * kFF * kD], g_w1t_l[(size_t)kE * kFF * kD];
__device__ __half g_w2t_h[(size_t)kE * kFF * kD], g_w2t_l[(size_t)kE * kFF * kD];

// ==================== PTX helpers (base sm_103 features only) ====================
__device__ __forceinline__ uint32_t smem_u32(const void* p) {
    uint32_t a;
    asm("{ .reg .u64 t; cvta.to.shared.u64 t, %1; cvt.u32.u64 %0, t; }" : "=r"(a) : "l"(p));
    return a;
}

__device__ __forceinline__ void cp_async16(uint32_t s, const void* g, int sz) {
    asm volatile("cp.async.cg.shared.global [%0], [%1], 16, %2;"
                 :: "r"(s), "l"(g), "r"(sz) : "memory");
}
#define CP_COMMIT()  asm volatile("cp.async.commit_group;" ::: "memory")
#define CP_WAIT(n)   asm volatile("cp.async.wait_group %0;" :: "n"(n) : "memory")

__device__ __forceinline__ void ldsm_x4(uint32_t& r0, uint32_t& r1, uint32_t& r2,
                                        uint32_t& r3, uint32_t addr) {
    asm volatile("ldmatrix.sync.aligned.m8n8.x4.shared.b16 {%0,%1,%2,%3}, [%4];"
                 : "=r"(r0), "=r"(r1), "=r"(r2), "=r"(r3) : "r"(addr));
}
__device__ __forceinline__ void ldsm_x4_t(uint32_t& r0, uint32_t& r1, uint32_t& r2,
                                          uint32_t& r3, uint32_t addr) {
    asm volatile("ldmatrix.sync.aligned.m8n8.x4.trans.shared.b16 {%0,%1,%2,%3}, [%4];"
                 : "=r"(r0), "=r"(r1), "=r"(r2), "=r"(r3) : "r"(addr));
}

__device__ __forceinline__ void mma16816(float* d, const uint32_t* a,
                                         uint32_t b0, uint32_t b1) {
    asm volatile("mma.sync.aligned.m16n8k16.row.col.f32.f16.f16.f32 "
                 "{%0,%1,%2,%3}, {%4,%5,%6,%7}, {%8,%9}, {%0,%1,%2,%3};"
                 : "+f"(d[0]), "+f"(d[1]), "+f"(d[2]), "+f"(d[3])
                 : "r"(a[0]), "r"(a[1]), "r"(a[2]), "r"(a[3]), "r"(b0), "r"(b1));
}

// pack two floats into half2 (hi only)
__device__ __forceinline__ uint32_t pack2h(float f0, float f1) {
    __half2 hv = __floats2half2_rn(f0, f1);
    return *reinterpret_cast<uint32_t*>(&hv);
}
// split into hi + lo half2 planes
__device__ __forceinline__ void split2h(float f0, float f1, uint32_t& h, uint32_t& l) {
    __half2 hv = __floats2half2_rn(f0, f1);
    float r0 = f0 - __half2float(__low2half(hv));
    float r1 = f1 - __half2float(__high2half(hv));
    __half2 lv = __floats2half2_rn(r0, r1);
    h = *reinterpret_cast<uint32_t*>(&hv);
    l = *reinterpret_cast<uint32_t*>(&lv);
}

// ==================== mma.sync 2-pass fp16 GEMM ====================
// Block 128x128, 256 threads (8 warps, 4Mx2N), warp tile 32x64, K-chunk 32.
// Planes per stage: Ah, Bh, Bl (XOR-swizzled 64B rows), 3-stage cp.async.
constexpr int kPlaneB = 128 * 64;              // 8192 B per plane
constexpr int kStageB = 3 * kPlaneB;           // Ah Bh Bl = 24576
constexpr int GEMM_SMEM = 3 * kStageB;         // 73728

__device__ __forceinline__ uint32_t swz(int row, int cb) {
    return (uint32_t)(row * 64 + ((((cb >> 4) ^ ((row >> 1) & 3))) << 4));
}

struct GemmPtrs {
    const __half *aH0, *aH1;
    const __half *bH0, *bL0, *bH1, *bL1;
    int v0, v1, c8;
};

__device__ __forceinline__ void fill_stage(uint32_t sb, int k0, const GemmPtrs& P)
{
    int row = threadIdx.x >> 2;                 // 0..63
    int cb  = (threadIdx.x & 3) * 16;
    uint32_t o0 = swz(row, cb);
    uint32_t o1 = o0 + 64 * 64;
    int g = k0 + P.c8;
    cp_async16(sb + o0,             P.aH0 + g, P.v0 ? 16 : 0);
    cp_async16(sb + o1,             P.aH1 + g, P.v1 ? 16 : 0);
    cp_async16(sb + kPlaneB + o0,   P.bH0 + g, 16);
    cp_async16(sb + kPlaneB + o1,   P.bH1 + g, 16);
    cp_async16(sb + 2*kPlaneB + o0, P.bL0 + g, 16);
    cp_async16(sb + 2*kPlaneB + o1, P.bL1 + g, 16);
}

// mode 0: C = acc + bias (fp32)
// mode 1: relu(acc+bias) -> Chi (fp16 hi only)
// mode 2: (acc+bias)*scale -> Chi (+Clo if non-null)
__device__ __forceinline__ void gemm_tc(
    const __half* __restrict__ Ah,
    const __half* __restrict__ Bh, const __half* __restrict__ Bl,
    const float* __restrict__ bias, int K, int count, const int* __restrict__ list,
    int mode, float* __restrict__ C,
    __half* __restrict__ Chi, __half* __restrict__ Clo, int ldc,
    float scale)
{
    extern __shared__ char sm[];
    const int tid  = threadIdx.x;
    const int wid  = tid >> 5, lane = tid & 31;
    const int rowBase = blockIdx.y * 128;
    const int colBase = blockIdx.x * 128;
    if (rowBase >= count) return;

    GemmPtrs P;
    {
        int r0 = tid >> 2;
        int gr0 = rowBase + r0, gr1 = rowBase + r0 + 64;
        P.v0 = gr0 < count;
        P.v1 = gr1 < count;
        int rr0 = P.v0 ? (list ? list[gr0] : gr0) : 0;
        int rr1 = P.v1 ? (list ? list[gr1] : gr1) : 0;
        P.aH0 = Ah + (size_t)rr0 * K;
        P.aH1 = Ah + (size_t)rr1 * K;
        P.bH0 = Bh + (size_t)(colBase + r0) * K;
        P.bH1 = Bh + (size_t)(colBase + r0 + 64) * K;
        P.bL0 = Bl + (size_t)(colBase + r0) * K;
        P.bL1 = Bl + (size_t)(colBase + r0 + 64) * K;
        P.c8  = (tid & 3) * 8;
    }
    const uint32_t smb = smem_u32(sm);

    const int wM = (wid & 3) * 32;
    const int wN = (wid >> 2) * 64;

    float acc[2][8][4];
    #pragma unroll
    for (int i = 0; i < 2; i++)
        #pragma unroll
        for (int j = 0; j < 8; j++)
            #pragma unroll
            for (int d = 0; d < 4; d++) acc[i][j][d] = 0.f;

    // precomputed swizzled ldsm offsets
    const int aCol = (lane >> 4) * 16;
    const int bRow = (lane & 7) + ((lane >> 4) & 1) * 8;
    const int bCol = ((lane >> 3) & 1) * 16;
    uint32_t offA[2][2], offB[4][2];
    #pragma unroll
    for (int mi = 0; mi < 2; mi++)
        #pragma unroll
        for (int s = 0; s < 2; s++)
            offA[mi][s] = swz(wM + mi * 16 + (lane & 15), s * 32 + aCol);
    #pragma unroll
    for (int nj = 0; nj < 4; nj++)
        #pragma unroll
        for (int s = 0; s < 2; s++)
            offB[nj][s] = kPlaneB + swz(wN + nj * 16 + bRow, s * 32 + bCol);

    const int nc = K / 32;
    fill_stage(smb, 0, P);
    CP_COMMIT();
    fill_stage(smb + kStageB, 32, P);
    CP_COMMIT();

    int buf = 0;
    for (int c = 0; c < nc; c++) {
        if (c + 1 < nc) { CP_WAIT(1); } else { CP_WAIT(0); }
        __syncthreads();
        if (c + 2 < nc) {
            int nb = buf + 2; if (nb >= 3) nb -= 3;
            fill_stage(smb + nb * kStageB, (c + 2) * 32, P);
            CP_COMMIT();
        }

        uint32_t st = smb + buf * kStageB;
        #pragma unroll
        for (int s = 0; s < 2; s++) {
            uint32_t ah[2][4];
            #pragma unroll
            for (int mi = 0; mi < 2; mi++)
                ldsm_x4(ah[mi][0], ah[mi][1], ah[mi][2], ah[mi][3], st + offA[mi][s]);
            #pragma unroll
            for (int njp = 0; njp < 4; njp++) {
                uint32_t rb = st + offB[njp][s];
                uint32_t bh[4], bl[4];
                ldsm_x4(bh[0], bh[1], bh[2], bh[3], rb);
                ldsm_x4(bl[0], bl[1], bl[2], bl[3], rb + kPlaneB);
                #pragma unroll
                for (int mi = 0; mi < 2; mi++) {
                    #pragma unroll
                    for (int half = 0; half < 2; half++) {
                        float* d = acc[mi][njp * 2 + half];
                        mma16816(d, ah[mi], bh[half * 2], bh[half * 2 + 1]);
                        mma16816(d, ah[mi], bl[half * 2], bl[half * 2 + 1]);
                    }
                }
            }
        }
        buf = (buf < 2) ? buf + 1 : 0;
    }

    #pragma unroll
    for (int mi = 0; mi < 2; mi++) {
        #pragma unroll
        for (int dd = 0; dd < 2; dd++) {
            int lrow = rowBase + wM + mi * 16 + (lane >> 2) + dd * 8;
            if (lrow >= count) continue;
            int orow = list ? list[lrow] : lrow;
            #pragma unroll
            for (int nj = 0; nj < 8; nj++) {
                int n = colBase + wN + nj * 8 + (lane & 3) * 2;
                float v0 = acc[mi][nj][dd * 2 + 0] + bias[n];
                float v1 = acc[mi][nj][dd * 2 + 1] + bias[n + 1];
                if (mode == 0) {
                    *reinterpret_cast<float2*>(C + (size_t)orow * ldc + n)
                        = make_float2(v0, v1);
                } else {
                    if (mode == 1) { v0 = fmaxf(v0, 0.f); v1 = fmaxf(v1, 0.f); }
                    else           { v0 *= scale; v1 *= scale; }
                    size_t o = (size_t)orow * ldc + n;
                    if (Clo) {
                        uint32_t hh, ll;
                        split2h(v0, v1, hh, ll);
                        *reinterpret_cast<uint32_t*>(Chi + o) = hh;
                        *reinterpret_cast<uint32_t*>(Clo + o) = ll;
                    } else {
                        *reinterpret_cast<uint32_t*>(Chi + o) = pack2h(v0, v1);
                    }
                }
            }
        }
    }
}

// ---------------- GEMM wrappers ----------------
__global__ void __launch_bounds__(256, 2) qkv_tc(const float* bq, const float* bk, const float* bv)
{
    int z = blockIdx.z;
    const __half* bh = g_w4t_h + (size_t)z * kD * kD;
    const __half* bl = g_w4t_l + (size_t)z * kD * kD;
    __half* ch = (z == 0) ? g_qb_h : (z == 1) ? g_kb_h : g_vb_h;
    __half* cl = (z == 0) ? nullptr : (z == 1) ? g_kb_l : g_vb_l;
    const float* bias = (z == 0) ? bq : (z == 1) ? bk : bv;
    float scale = (z == 0) ? 0.125f : 1.0f;
    gemm_tc(g_xb_h, bh, bl, bias, kD, kNT, nullptr, 2, nullptr, ch, cl, kD, scale);
}

__global__ void __launch_bounds__(256, 2) proj_tc(const float* bo)
{
    gemm_tc(g_ab_h, g_w4t_h + (size_t)3 * kD * kD, g_w4t_l + (size_t)3 * kD * kD,
            bo, kD, kNT, nullptr, 0, g_proj, nullptr, nullptr, kD, 1.f);
}

__global__ void __launch_bounds__(256, 2) moe1_tc(const float* b1e)
{
    int e = blockIdx.z;
    int cnt = g_cnt[e];
    gemm_tc(g_x1b_h,
            g_w1t_h + (size_t)e * kFF * kD, g_w1t_l + (size_t)e * kFF * kD,
            b1e + (size_t)e * kFF, kD, cnt, g_list + e * kNT,
            1, nullptr, g_hb_h, nullptr, kFF, 1.f);
}

__global__ void __launch_bounds__(256, 2) moe2_tc(const float* b2e)
{
    int e = blockIdx.z;
    int cnt = g_cnt[e];
    gemm_tc(g_hb_h,
            g_w2t_h + (size_t)e * kFF * kD, g_w2t_l + (size_t)e * kFF * kD,
            b2e + (size_t)e * kD, kFF, cnt, g_list + e * kNT,
            0, g_y, nullptr, nullptr, kD, 1.f);
}

// ==================== HMMA flash attention (causal, 2-pass fp16) ====================
// Q pre-scaled by 0.125 in qkv epilogue (hi only). q-tile 128, kv-tile 64.
constexpr int kARS    = 144;                   // padded row bytes
constexpr int kAPlane = 64 * kARS;             // 9216
constexpr int kAStage = 4 * kAPlane;           // Kh Kl Vh Vl = 36864
constexpr int ATTN_SMEM = 2 * kAStage;         // 73728

__device__ __forceinline__ void fill_kv(uint32_t dst, int b, int h, int kbase)
{
    const __half* srcs[4] = {g_kb_h, g_kb_l, g_vb_h, g_vb_l};
    #pragma unroll
    for (int i = 0; i < 8; i++) {
        int lin = threadIdx.x + 256 * i;
        int ch = lin & 7, row = (lin >> 3) & 63, pl = lin >> 9;
        const __half* src = srcs[pl]
            + ((size_t)(b * kT + kbase + row) * kD + h * 64 + ch * 8);
        cp_async16(dst + pl * kAPlane + row * kARS + ch * 16, src, 16);
    }
}

__global__ void __launch_bounds__(256) attn_tc()
{
    extern __shared__ char sa[];
    const uint32_t smb = smem_u32(sa);
    const int tid = threadIdx.x, wid = tid >> 5, lane = tid & 31;
    const int qt = gridDim.x - 1 - blockIdx.x;   // longest-first
    const int bh = blockIdx.y;
    const int b = bh >> 4, h = bh & 15;
    const int qb = qt * 128;
    const int wr0 = qb + wid * 16;

    // ---- load Q tile (128 x 64, hi only) into stage1 region ----
    #pragma unroll
    for (int i = 0; i < 4; i++) {
        int lin = tid + 256 * i;
        int ch = lin & 7, row = lin >> 3;
        const __half* src = g_qb_h
            + ((size_t)(b * kT + qb + row) * kD + h * 64 + ch * 8);
        cp_async16(smb + kAStage + row * kARS + ch * 16, src, 16);
    }
    CP_COMMIT();
    fill_kv(smb, b, h, 0);
    CP_COMMIT();
    CP_WAIT(0);
    __syncthreads();

    // ---- Q fragments to registers ----
    uint32_t qh[4][4];
    #pragma unroll
    for (int ks = 0; ks < 4; ks++) {
        uint32_t addr = smb + kAStage + (wid * 16 + (lane & 15)) * kARS
                      + ks * 32 + (lane >> 4) * 16;
        ldsm_x4(qh[ks][0], qh[ks][1], qh[ks][2], qh[ks][3], addr);
    }

    float m0 = -1e30f, m1 = -1e30f, l0 = 0.f, l1 = 0.f;
    float o[8][4];
    #pragma unroll
    for (int g = 0; g < 8; g++)
        #pragma unroll
        for (int d = 0; d < 4; d++) o[g][d] = 0.f;

    const int ktmax = 2 * qt + 2;
    for (int kt = 0; kt < ktmax; kt++) {
        CP_WAIT(0);
        __syncthreads();
        if (kt + 1 < ktmax) {
            fill_kv(smb + ((kt + 1) & 1) * kAStage, b, h, (kt + 1) * 64);
            CP_COMMIT();
        }

        const int kbase = kt * 64;
        if (kbase <= wr0 + 15) {
            const uint32_t st = smb + (kt & 1) * kAStage;

            // ---- S = Q K^T (2-pass) ----
            float s[8][4];
            #pragma unroll
            for (int j = 0; j < 8; j++)
                #pragma unroll
                for (int d = 0; d < 4; d++) s[j][d] = 0.f;

            #pragma unroll
            for (int ks = 0; ks < 4; ks++) {
                #pragma unroll
                for (int ng = 0; ng < 4; ng++) {
                    uint32_t a = st + (ng * 16 + (lane & 7) + (lane >> 4) * 8) * kARS
                               + ks * 32 + ((lane >> 3) & 1) * 16;
                    uint32_t k0, k1, k2, k3, e0, e1, e2, e3;
                    ldsm_x4(k0, k1, k2, k3, a);
                    ldsm_x4(e0, e1, e2, e3, a + kAPlane);
                    mma16816(s[2*ng],   qh[ks], k0, k1);
                    mma16816(s[2*ng],   qh[ks], e0, e1);
                    mma16816(s[2*ng+1], qh[ks], k2, k3);
                    mma16816(s[2*ng+1], qh[ks], e2, e3);
                }
            }

            // ---- mask (straddling tiles only) ----
            const int r0 = wr0 + (lane >> 2), r1 = r0 + 8;
            if (kbase + 63 > wr0) {
                #pragma unroll
                for (int j = 0; j < 8; j++) {
                    int c = kbase + j * 8 + (lane & 3) * 2;
                    if (c > r0)     s[j][0] = -1e30f;
                    if (c + 1 > r0) s[j][1] = -1e30f;
                    if (c > r1)     s[j][2] = -1e30f;
                    if (c + 1 > r1) s[j][3] = -1e30f;
                }
            }

            // ---- online softmax ----
            float rm0 = -1e30f, rm1 = -1e30f;
            #pragma unroll
            for (int j = 0; j < 8; j++) {
                rm0 = fmaxf(rm0, fmaxf(s[j][0], s[j][1]));
                rm1 = fmaxf(rm1, fmaxf(s[j][2], s[j][3]));
            }
            rm0 = fmaxf(rm0, __shfl_xor_sync(0xffffffffu, rm0, 1));
            rm0 = fmaxf(rm0, __shfl_xor_sync(0xffffffffu, rm0, 2));
            rm1 = fmaxf(rm1, __shfl_xor_sync(0xffffffffu, rm1, 1));
            rm1 = fmaxf(rm1, __shfl_xor_sync(0xffffffffu, rm1, 2));
            float mn0 = fmaxf(m0, rm0), mn1 = fmaxf(m1, rm1);
            float cr0 = __expf(m0 - mn0), cr1 = __expf(m1 - mn1);
            m0 = mn0; m1 = mn1;
            float ps0 = 0.f, ps1 = 0.f;
            #pragma unroll
            for (int j = 0; j < 8; j++) {
                s[j][0] = __expf(s[j][0] - m0);
                s[j][1] = __expf(s[j][1] - m0);
                s[j][2] = __expf(s[j][2] - m1);
                s[j][3] = __expf(s[j][3] - m1);
                ps0 += s[j][0] + s[j][1];
                ps1 += s[j][2] + s[j][3];
            }
            ps0 += __shfl_xor_sync(0xffffffffu, ps0, 1);
            ps0 += __shfl_xor_sync(0xffffffffu, ps0, 2);
            ps1 += __shfl_xor_sync(0xffffffffu, ps1, 1);
            ps1 += __shfl_xor_sync(0xffffffffu, ps1, 2);
            l0 = l0 * cr0 + ps0;
            l1 = l1 * cr1 + ps1;
            #pragma unroll
            for (int g = 0; g < 8; g++) {
                o[g][0] *= cr0; o[g][1] *= cr0;
                o[g][2] *= cr1; o[g][3] *= cr1;
            }

            // ---- O += P V (2-pass, P packed in registers) ----
            #pragma unroll
            for (int t = 0; t < 4; t++) {
                uint32_t ph[4];
                ph[0] = pack2h(s[2*t][0],   s[2*t][1]);
                ph[1] = pack2h(s[2*t][2],   s[2*t][3]);
                ph[2] = pack2h(s[2*t+1][0], s[2*t+1][1]);
                ph[3] = pack2h(s[2*t+1][2], s[2*t+1][3]);
                #pragma unroll
                for (int dg = 0; dg < 4; dg++) {
                    uint32_t a = st + 2 * kAPlane
                               + (t * 16 + (lane & 7) + ((lane >> 3) & 1) * 8) * kARS
                               + dg * 32 + (lane >> 4) * 16;
                    uint32_t v0, v1, v2, v3, w0, w1, w2, w3;
                    ldsm_x4_t(v0, v1, v2, v3, a);
                    ldsm_x4_t(w0, w1, w2, w3, a + kAPlane);
                    mma16816(o[2*dg],   ph, v0, v1);
                    mma16816(o[2*dg],   ph, w0, w1);
                    mma16816(o[2*dg+1], ph, v2, v3);
                    mma16816(o[2*dg+1], ph, w2, w3);
                }
            }
        }
    }

    // ---- epilogue: O/l -> fp16 hi plane ----
    const float inv0 = 1.f / l0, inv1 = 1.f / l1;
    const size_t tok0 = (size_t)(b * kT) + wr0 + (lane >> 2);
    #pragma unroll
    for (int g = 0; g < 8; g++) {
        int col = h * 64 + g * 8 + (lane & 3) * 2;
        *reinterpret_cast<uint32_t*>(g_ab_h + tok0 * kD + col)
            = pack2h(o[g][0] * inv0, o[g][1] * inv0);
        *reinterpret_cast<uint32_t*>(g_ab_h + (tok0 + 8) * kD + col)
            = pack2h(o[g][2] * inv1, o[g][3] * inv1);
    }
}

// ---------------- conversion kernels ----------------
__global__ void convert_x(const float* __restrict__ x)
{
    int i = blockIdx.x * 256 + threadIdx.x;
    float4 v = ((const float4*)x)[i];
    size_t o = (size_t)i * 4;
    *reinterpret_cast<uint32_t*>(g_xb_h + o)     = pack2h(v.x, v.y);
    *reinterpret_cast<uint32_t*>(g_xb_h + o + 2) = pack2h(v.z, v.w);
}

__device__ __forceinline__ void transpose_body(
    const float* __restrict__ src, __half* __restrict__ hi,
    __half* __restrict__ lo, int K, int N)
{
    __shared__ float tile[32][33];
    int bn = blockIdx.x * 32, bk = blockIdx.y * 32;
    int tx = threadIdx.x, ty = threadIdx.y;
    #pragma unroll
    for (int i = 0; i < 32; i += 8)
        tile[ty + i][tx] = src[(size_t)(bk + ty + i) * N + bn + tx];
    __syncthreads();
    #pragma unroll
    for (int i = 0; i < 32; i += 8) {
        float v = tile[tx][ty + i];
        __half hh = __float2half_rn(v);
        size_t o = (size_t)(bn + ty + i) * K + bk + tx;
        hi[o] = hh;
        lo[o] = __float2half_rn(v - __half2float(hh));
    }
}

__global__ void transpose_qkvo(const float* Wq, const float* Wk, const float* Wv, const float* Wo)
{
    int z = blockIdx.z;
    const float* src = (z == 0) ? Wq : (z == 1) ? Wk : (z == 2) ? Wv : Wo;
    transpose_body(src, g_w4t_h + (size_t)z * kD * kD, g_w4t_l + (size_t)z * kD * kD, kD, kD);
}

__global__ void transpose_w1(const float* W1e)
{
    int e = blockIdx.z;
    size_t off = (size_t)e * kD * kFF;
    transpose_body(W1e + off, g_w1t_h + off, g_w1t_l + off, kD, kFF);
}

__global__ void transpose_w2(const float* W2e)
{
    int e = blockIdx.z;
    size_t off = (size_t)e * kFF * kD;
    transpose_body(W2e + off, g_w2t_h + off, g_w2t_l + off, kFF, kD);
}

// ---------------- add + layernorm ----------------
__device__ __forceinline__ float block_sum_256(float v, float* red)
{
    int tid = threadIdx.x;
    #pragma unroll
    for (int o = 16; o; o >>= 1) v += __shfl_xor_sync(0xffffffffu, v, o);
    if ((tid & 31) == 0) red[tid >> 5] = v;
    __syncthreads();
    if (tid < 8) {
        float x = red[tid];
        #pragma unroll
        for (int o = 4; o; o >>= 1) x += __shfl_xor_sync(0xffu, x, o);
        if (tid == 0) red[0] = x;
    }
    __syncthreads();
    float r = red[0];
    __syncthreads();
    return r;
}

__device__ __forceinline__ void add_ln_body(
    const float* __restrict__ A, const float* __restrict__ Bb,
    const float* __restrict__ gw, const float* __restrict__ bw,
    float* __restrict__ out, __half* __restrict__ oh)
{
    __shared__ float red[8];
    int t = blockIdx.x, tid = threadIdx.x;
    float4 av = ((const float4*)(A  + (size_t)t * kD))[tid];
    float4 bv = ((const float4*)(Bb + (size_t)t * kD))[tid];
    float vx = av.x + bv.x, vy = av.y + bv.y, vz = av.z + bv.z, vw = av.w + bv.w;
    float ssum = block_sum_256(vx + vy + vz + vw, red);
    float mu = ssum * (1.0f / kD);
    float dx = vx - mu, dy = vy - mu, dz = vz - mu, dw = vw - mu;
    float sq = block_sum_256(dx*dx + dy*dy + dz*dz + dw*dw, red);
    float rstd = rsqrtf(sq * (1.0f / kD) + kEPS);
    float4 gv = ((const float4*)gw)[tid];
    float4 be = ((const float4*)bw)[tid];
    float ovv[4] = {dx*rstd*gv.x + be.x, dy*rstd*gv.y + be.y,
                    dz*rstd*gv.z + be.z, dw*rstd*gv.w + be.w};
    ((float4*)(out + (size_t)t * kD))[tid] = make_float4(ovv[0], ovv[1], ovv[2], ovv[3]);
    if (oh) {
        size_t o = (size_t)t * kD + tid * 4;
        *reinterpret_cast<uint32_t*>(oh + o)     = pack2h(ovv[0], ovv[1]);
        *reinterpret_cast<uint32_t*>(oh + o + 2) = pack2h(ovv[2], ovv[3]);
    }
}

__global__ void ln1_kernel(const float* __restrict__ x,
                           const float* __restrict__ g, const float* __restrict__ b)
{
    add_ln_body(x, g_proj, g, b, g_x1, g_x1b_h);
}

__global__ void ln2_kernel(const float* __restrict__ g, const float* __restrict__ b,
                           float* __restrict__ out)
{
    add_ln_body(g_x1, g_y, g, b, out, nullptr);
}

// ---------------- MoE gate (top-1 argmax) ----------------
__global__ void zero_cnt()
{
    if (threadIdx.x < kE) g_cnt[threadIdx.x] = 0;
}

__global__ void gate_kernel(const float* __restrict__ Wg, const float* __restrict__ bg)
{
    int t = blockIdx.x, tid = threadIdx.x;
    float a0 = 0.f, a1 = 0.f, a2 = 0.f, a3 = 0.f;
    const float* xr = g_x1 + (size_t)t * kD;
    for (int d = tid; d < kD; d += 128) {
        float xv = xr[d];
        float4 w = ((const float4*)Wg)[d];
        a0 = fmaf(xv, w.x, a0);
        a1 = fmaf(xv, w.y, a1);
        a2 = fmaf(xv, w.z, a2);
        a3 = fmaf(xv, w.w, a3);
    }
    __shared__ float rsm[4][128];
    rsm[0][tid] = a0; rsm[1][tid] = a1; rsm[2][tid] = a2; rsm[3][tid] = a3;
    __syncthreads();
    for (int s = 64; s > 0; s >>= 1) {
        if (tid < s) {
            #pragma unroll
            for (int e = 0; e < 4; e++) rsm[e][tid] += rsm[e][tid + s];
        }
        __syncthreads();
    }
    if (tid == 0) {
        float sc[4];
        #pragma unroll
        for (int e = 0; e < 4; e++) sc[e] = rsm[e][0] + bg[e];
        int best = 0; float bvv = sc[0];
        #pragma unroll
        for (int e = 1; e < 4; e++) {
            if (sc[e] > bvv) { bvv = sc[e]; best = e; }
        }
        int pos = atomicAdd(&g_cnt[best], 1);
        g_list[best * kNT + pos] = t;
    }
}

// ---------------- launch ----------------
extern "C" void kernel_launch(void* const* d_in, const int* in_sizes, int n_in,
                              void* d_out, int out_size)
{
    const float* x    = (const float*)d_in[0];
    const float* Wq   = (const float*)d_in[2];
    const float* bq   = (const float*)d_in[3];
    const float* Wk   = (const float*)d_in[4];
    const float* bk   = (const float*)d_in[5];
    const float* Wv   = (const float*)d_in[6];
    const float* bv   = (const float*)d_in[7];
    const float* Wo   = (const float*)d_in[8];
    const float* bo   = (const float*)d_in[9];
    const float* ln1g = (const float*)d_in[10];
    const float* ln1b = (const float*)d_in[11];
    const float* Wg   = (const float*)d_in[12];
    const float* bg   = (const float*)d_in[13];
    const float* W1e  = (const float*)d_in[14];
    const float* b1e  = (const float*)d_in[15];
    const float* W2e  = (const float*)d_in[16];
    const float* b2e  = (const float*)d_in[17];
    const float* ln2g = (const float*)d_in[18];
    const float* ln2b = (const float*)d_in[19];
    float* out = (float*)d_out;

    cudaFuncSetAttribute(attn_tc, cudaFuncAttributeMaxDynamicSharedMemorySize, ATTN_SMEM);
    cudaFuncSetAttribute(qkv_tc,  cudaFuncAttributeMaxDynamicSharedMemorySize, GEMM_SMEM);
    cudaFuncSetAttribute(proj_tc, cudaFuncAttributeMaxDynamicSharedMemorySize, GEMM_SMEM);
    cudaFuncSetAttribute(moe1_tc, cudaFuncAttributeMaxDynamicSharedMemorySize, GEMM_SMEM);
    cudaFuncSetAttribute(moe2_tc, cudaFuncAttributeMaxDynamicSharedMemorySize, GEMM_SMEM);

    // side stream for prep work that can overlap the main chain
    cudaStream_t side;
    cudaEvent_t evFork, evJoin1, evJoin2;
    cudaStreamCreateWithFlags(&side, cudaStreamNonBlocking);
    cudaEventCreateWithFlags(&evFork, cudaEventDisableTiming);
    cudaEventCreateWithFlags(&evJoin1, cudaEventDisableTiming);
    cudaEventCreateWithFlags(&evJoin2, cudaEventDisableTiming);

    cudaEventRecord(evFork, 0);
    cudaStreamWaitEvent(side, evFork, 0);
    convert_x<<<kNT * kD / 4 / 256, 256, 0, side>>>(x);
    cudaEventRecord(evJoin1, side);
    transpose_w1<<<dim3(kFF/32, kD/32, kE), dim3(32, 8), 0, side>>>(W1e);
    transpose_w2<<<dim3(kD/32, kFF/32, kE), dim3(32, 8), 0, side>>>(W2e);
    cudaEventRecord(evJoin2, side);

    // main chain: attention path
    transpose_qkvo<<<dim3(kD/32, kD/32, 4), dim3(32, 8)>>>(Wq, Wk, Wv, Wo);
    cudaStreamWaitEvent(0, evJoin1, 0);
    qkv_tc<<<dim3(kD/128, kNT/128, 3), 256, GEMM_SMEM>>>(bq, bk, bv);
    attn_tc<<<dim3(kT/128, kB*kH), 256, ATTN_SMEM>>>();
    proj_tc<<<dim3(kD/128, kNT/128), 256, GEMM_SMEM>>>(bo);
    ln1_kernel<<<kNT, 256>>>(x, ln1g, ln1b);

    // MoE path
    zero_cnt<<<1, 32>>>();
    gate_kernel<<<kNT, 128>>>(Wg, bg);
    cudaStreamWaitEvent(0, evJoin2, 0);
    moe1_tc<<<dim3(kFF/128, kNT/128, kE), 256, GEMM_SMEM>>>(b1e);
    moe2_tc<<<dim3(kD/128, kNT/128, kE), 256, GEMM_SMEM>>>(b2e);
    ln2_kernel<<<kNT, 256>>>(ln2g, ln2b, out);
}